// round 14
// baseline (speedup 1.0000x reference)
#include <cuda_runtime.h>
#include <cuda_bf16.h>
#include <cstdint>

// ---------------------------------------------------------------------------
// transformer_75419625718098: talking-heads causal attention
// B=1, N=2048, C=1024, H=16, D=64
// Round 14: R13 (767.2us) + qkv split-K x2 (combine fused into qkv_split)
// + out-proj split-K x4. Mechanism: wave-quantization fill (validated R13).
// ---------------------------------------------------------------------------

#define NTOK 2048
#define NHEAD 16
#define HDIM 64
#define CDIM 1024
#define NN (2048*2048)

// 64-wide gemm (QK / PV / out-proj)
#define STG_BYTES 12288
#define GEMM_SMEM (4 * STG_BYTES)          // 49152
// 128-wide gemm (qkv)
#define STG128 16384
#define GEMM128_SMEM (4 * STG128)          // 65536

// ------------------------- device scratch ----------------------------------
__device__ float g_qkv0[2048 * 3072];           // qkv split-K partial 0
__device__ float g_qkv1[2048 * 3072];           // qkv split-K partial 1
__device__ float g_bufA[(long long)NHEAD * NN]; // S0 fp32 -> Pm hi/lo planes
__device__ float g_bufB[(long long)NHEAD * NN]; // s (mixed logits)
__device__ float g_m   [NHEAD * NTOK];
__device__ float g_invl[NHEAD * NTOK];
__device__ float g_o2p [4LL * 2048 * 1024];     // PV split-K partials (x4)
__device__ float g_outp[4LL * 2048 * 1024];     // out-proj split-K partials (x4)
// (hi,lo) bf16 planes
__device__ __nv_bfloat16 g_xh [2048 * 1024], g_xl [2048 * 1024];
__device__ __nv_bfloat16 g_wqh[3072 * 1024], g_wql[3072 * 1024];
__device__ __nv_bfloat16 g_woh[1024 * 1024], g_wol[1024 * 1024];
__device__ __nv_bfloat16 g_qnh[NHEAD * NTOK * HDIM], g_qnl[NHEAD * NTOK * HDIM];
__device__ __nv_bfloat16 g_knh[NHEAD * NTOK * HDIM], g_knl[NHEAD * NTOK * HDIM];
__device__ __nv_bfloat16 g_vth[NHEAD * HDIM * NTOK], g_vtl[NHEAD * HDIM * NTOK];
__device__ __nv_bfloat16 g_o2h[2048 * 1024], g_o2l[2048 * 1024];

// fast exp on the FMA pipe
__device__ __forceinline__ float fexp(float x) {
    float t = fmaxf(x * 1.4426950408889634f, -126.0f);
    int ei = __float2int_rd(t);
    float f = t - (float)ei;
    float y = 0.69314718055994531f * f;
    float p = fmaf(y, 1.3888889e-3f, 8.3333333e-3f);
    p = fmaf(y, p, 4.1666667e-2f);
    p = fmaf(y, p, 1.6666667e-1f);
    p = fmaf(y, p, 0.5f);
    p = fmaf(y, p, 1.0f);
    p = fmaf(y, p, 1.0f);
    return p * __int_as_float((ei + 127) << 23);
}

__device__ __forceinline__ uint2 pack2_bf16(float x0, float x1) {
    uint32_t hi;
    asm("cvt.rn.bf16x2.f32 %0, %1, %2;" : "=r"(hi) : "f"(x1), "f"(x0));
    float h0 = __uint_as_float(hi << 16);
    float h1 = __uint_as_float(hi & 0xFFFF0000u);
    uint32_t lo;
    asm("cvt.rn.bf16x2.f32 %0, %1, %2;" : "=r"(lo) : "f"(x1 - h1), "f"(x0 - h0));
    return make_uint2(hi, lo);
}

__device__ __forceinline__ void mma_bf16(float* c, const uint32_t* a, const uint32_t* b) {
    asm volatile(
        "mma.sync.aligned.m16n8k16.row.col.f32.bf16.bf16.f32 "
        "{%0,%1,%2,%3},{%4,%5,%6,%7},{%8,%9},{%0,%1,%2,%3};"
        : "+f"(c[0]), "+f"(c[1]), "+f"(c[2]), "+f"(c[3])
        : "r"(a[0]), "r"(a[1]), "r"(a[2]), "r"(a[3]), "r"(b[0]), "r"(b[1]));
}

__device__ __forceinline__ void ldsm4(uint32_t* r, uint32_t addr) {
    asm volatile("ldmatrix.sync.aligned.m8n8.x4.shared.b16 {%0,%1,%2,%3}, [%4];"
                 : "=r"(r[0]), "=r"(r[1]), "=r"(r[2]), "=r"(r[3]) : "r"(addr));
}

// ---------------- pack fp32 -> hi/lo bf16 planes ----------------------------
__global__ void pack_planes(const float* __restrict__ s,
                            __nv_bfloat16* __restrict__ hi,
                            __nv_bfloat16* __restrict__ lo, int n)
{
    int i = (blockIdx.x * 256 + threadIdx.x) * 4;
    if (i >= n) return;
    float4 v = *(const float4*)(s + i);
    uint2 p01 = pack2_bf16(v.x, v.y);
    uint2 p23 = pack2_bf16(v.z, v.w);
    *(uint2*)(hi + i) = make_uint2(p01.x, p23.x);
    *(uint2*)(lo + i) = make_uint2(p01.y, p23.y);
}

// ------------- combine 4 split-K partials + pack to planes ------------------
__global__ void combine_pack4(const float* __restrict__ p0, const float* __restrict__ p1,
                              const float* __restrict__ p2, const float* __restrict__ p3,
                              __nv_bfloat16* __restrict__ hi, __nv_bfloat16* __restrict__ lo,
                              int n)
{
    int i = (blockIdx.x * 256 + threadIdx.x) * 4;
    if (i >= n) return;
    float4 a = *(const float4*)(p0 + i);
    float4 b = *(const float4*)(p1 + i);
    float4 c = *(const float4*)(p2 + i);
    float4 d = *(const float4*)(p3 + i);
    uint2 p01 = pack2_bf16(a.x + b.x + c.x + d.x, a.y + b.y + c.y + d.y);
    uint2 p23 = pack2_bf16(a.z + b.z + c.z + d.z, a.w + b.w + c.w + d.w);
    *(uint2*)(hi + i) = make_uint2(p01.x, p23.x);
    *(uint2*)(lo + i) = make_uint2(p01.y, p23.y);
}

// ------------- combine 4 split-K partials (fp32 out) ------------------------
__global__ void combine_out4(const float* __restrict__ p0, const float* __restrict__ p1,
                             const float* __restrict__ p2, const float* __restrict__ p3,
                             float* __restrict__ o, int n)
{
    int i = (blockIdx.x * 256 + threadIdx.x) * 4;
    if (i >= n) return;
    float4 a = *(const float4*)(p0 + i);
    float4 b = *(const float4*)(p1 + i);
    float4 c = *(const float4*)(p2 + i);
    float4 d = *(const float4*)(p3 + i);
    *(float4*)(o + i) = make_float4(a.x + b.x + c.x + d.x, a.y + b.y + c.y + d.y,
                                    a.z + b.z + c.z + d.z, a.w + b.w + c.w + d.w);
}

// ---------- ldmatrix split-bf16 GEMM (128x64): C = A * B^T ------------------
// mode 0: plain batched.  mode 1: causal tile skip (QK).
// mode 2: causal split-K x4 PV (z = 4*g+part, Keff = min(K, i0+128)).
// mode 3: plain split-K x4 (z = part, no batch).
__global__ void __launch_bounds__(256, 3)
gemm_lm(const __nv_bfloat16* __restrict__ Ah, const __nv_bfloat16* __restrict__ Al,
        const __nv_bfloat16* __restrict__ Bh, const __nv_bfloat16* __restrict__ Bl,
        float* __restrict__ C,
        int K, int lda, int ldb, int ldc,
        long long sA, long long sB, long long sC, long long ssplit, int mode)
{
    int j0 = blockIdx.x * 64;
    int i0 = blockIdx.y * 128;
    if (mode == 1 && j0 > i0 + 127) return;
    int bz = blockIdx.z;
    int g, part;
    if (mode == 2)      { g = bz >> 2; part = bz & 3; }
    else if (mode == 3) { g = 0;       part = bz;     }
    else                { g = bz;      part = 0;      }
    Ah += (long long)g * sA; Al += (long long)g * sA;
    Bh += (long long)g * sB; Bl += (long long)g * sB;
    C  += (long long)g * sC + (long long)part * ssplit;

    int ks = 0, ke = K;
    if (mode == 2) {
        int Keff = min(K, i0 + 128);
        int q1 = (Keff >> 2) & ~15;
        int q2 = (Keff >> 1) & ~15;
        int q3 = ((3 * Keff) >> 2) & ~15;
        ks = (part == 0) ? 0  : (part == 1) ? q1 : (part == 2) ? q2 : q3;
        ke = (part == 0) ? q1 : (part == 1) ? q2 : (part == 2) ? q3 : Keff;
    } else if (mode == 3) {
        int quarter = K >> 2;
        ks = part * quarter;
        ke = ks + quarter;
    }
    int KC = (ke - ks) >> 4;

    extern __shared__ char smem[];
    uint32_t sb0 = (uint32_t)__cvta_generic_to_shared(smem);

    int t = threadIdx.x;
    int lane = t & 31;
    int wid  = t >> 5;
    int wm   = (wid & 3) * 32;
    int wn   = (wid >> 2) * 32;

    uint32_t soff[3];
    const __nv_bfloat16* gsrc[3];
#pragma unroll
    for (int u = 0; u < 3; u++) {
        int q = t + u * 256;
        if (q < 512) {
            int plane = q >> 8, ca = q & 255;
            int row = ca >> 1, hf = ca & 1;
            gsrc[u] = (plane ? Al : Ah) + (long long)(i0 + row) * lda + hf * 8;
            soff[u] = plane * 4096 + (uint32_t)((ca ^ ((ca >> 3) & 1)) * 16);
        } else {
            int q2 = q - 512;
            int plane = q2 >> 7, cb = q2 & 127;
            int row = cb >> 1, hf = cb & 1;
            gsrc[u] = (plane ? Bl : Bh) + (long long)(j0 + row) * ldb + hf * 8;
            soff[u] = 8192 + plane * 2048 + (uint32_t)((cb ^ ((cb >> 3) & 1)) * 16);
        }
    }

#define ISSUE(cc)                                                             \
    do {                                                                      \
        uint32_t base_ = sb0 + (uint32_t)(((cc) & 3) * STG_BYTES);            \
        int k_ = ks + (cc) * 16;                                              \
        _Pragma("unroll")                                                     \
        for (int u = 0; u < 3; u++)                                           \
            asm volatile("cp.async.ca.shared.global [%0], [%1], 16;"          \
                         :: "r"(base_ + soff[u]), "l"(gsrc[u] + k_) : "memory"); \
    } while (0)

    uint32_t addrA[2][2], addrB[2][2];
#pragma unroll
    for (int mt = 0; mt < 2; mt++) {
        int row = wm + mt * 16 + (lane & 15);
        int hf = lane >> 4;
        int ca = row * 2 + hf;
        uint32_t ph = (uint32_t)((ca ^ ((ca >> 3) & 1)) * 16);
#pragma unroll
        for (int pl = 0; pl < 2; pl++) addrA[mt][pl] = sb0 + pl * 4096 + ph;
    }
#pragma unroll
    for (int ng = 0; ng < 2; ng++) {
        int n = wn + ng * 16 + ((lane >> 4) & 1) * 8 + (lane & 7);
        int hf = (lane >> 3) & 1;
        int cb = n * 2 + hf;
        uint32_t ph = (uint32_t)((cb ^ ((cb >> 3) & 1)) * 16);
#pragma unroll
        for (int pl = 0; pl < 2; pl++) addrB[ng][pl] = sb0 + 8192 + pl * 2048 + ph;
    }

#pragma unroll
    for (int s = 0; s < 3; s++) {
        if (s < KC) ISSUE(s);
        asm volatile("cp.async.commit_group;" ::: "memory");
    }

    float acc[2][4][4];
#pragma unroll
    for (int mt = 0; mt < 2; mt++)
#pragma unroll
        for (int nt = 0; nt < 4; nt++)
#pragma unroll
            for (int e = 0; e < 4; e++) acc[mt][nt][e] = 0.0f;

    for (int c = 0; c < KC; c++) {
        asm volatile("cp.async.wait_group 2;" ::: "memory");
        __syncthreads();
        {
            int s = c + 3;
            if (s < KC) ISSUE(s);
            asm volatile("cp.async.commit_group;" ::: "memory");
        }
        uint32_t st = (uint32_t)((c & 3) * STG_BYTES);

        uint32_t ah[2][4], al[2][4], bb[2][4];
        ldsm4(ah[0], addrA[0][0] + st);
        ldsm4(ah[1], addrA[1][0] + st);
        ldsm4(al[0], addrA[0][1] + st);
        ldsm4(al[1], addrA[1][1] + st);
        ldsm4(bb[0], addrB[0][0] + st);
        ldsm4(bb[1], addrB[1][0] + st);
#pragma unroll
        for (int mt = 0; mt < 2; mt++)
#pragma unroll
            for (int nt = 0; nt < 4; nt++)
                mma_bf16(acc[mt][nt], ah[mt], &bb[nt >> 1][(nt & 1) * 2]);
#pragma unroll
        for (int mt = 0; mt < 2; mt++)
#pragma unroll
            for (int nt = 0; nt < 4; nt++)
                mma_bf16(acc[mt][nt], al[mt], &bb[nt >> 1][(nt & 1) * 2]);
        ldsm4(bb[0], addrB[0][1] + st);
        ldsm4(bb[1], addrB[1][1] + st);
#pragma unroll
        for (int mt = 0; mt < 2; mt++)
#pragma unroll
            for (int nt = 0; nt < 4; nt++)
                mma_bf16(acc[mt][nt], ah[mt], &bb[nt >> 1][(nt & 1) * 2]);
    }
#undef ISSUE

    int gid = lane >> 2, tig = lane & 3;
#pragma unroll
    for (int mt = 0; mt < 2; mt++) {
        int r = i0 + wm + mt * 16 + gid;
#pragma unroll
        for (int nt = 0; nt < 4; nt++) {
            int cc = j0 + wn + nt * 8 + tig * 2;
            C[(long long)r * ldc + cc]           = acc[mt][nt][0];
            C[(long long)r * ldc + cc + 1]       = acc[mt][nt][1];
            C[(long long)(r + 8) * ldc + cc]     = acc[mt][nt][2];
            C[(long long)(r + 8) * ldc + cc + 1] = acc[mt][nt][3];
        }
    }
}

// ---------- ldmatrix split-bf16 GEMM (128x128): C = A * B^T (qkv) -----------
// split=1: K halved, part = blockIdx.z, C += part*ssplit (fp32 partials).
__global__ void __launch_bounds__(256, 2)
gemm_lm128(const __nv_bfloat16* __restrict__ Ah, const __nv_bfloat16* __restrict__ Al,
           const __nv_bfloat16* __restrict__ Bh, const __nv_bfloat16* __restrict__ Bl,
           float* __restrict__ C, int K, int lda, int ldb, int ldc,
           long long ssplit, int split)
{
    int j0 = blockIdx.x * 128;
    int i0 = blockIdx.y * 128;
    int ks = 0, Kloc = K;
    if (split) {
        Kloc = K >> 1;
        ks = blockIdx.z * Kloc;
        C += (long long)blockIdx.z * ssplit;
    }
    int KC = Kloc >> 4;

    extern __shared__ char smem[];
    uint32_t sb0 = (uint32_t)__cvta_generic_to_shared(smem);

    int t = threadIdx.x;
    int lane = t & 31;
    int wid  = t >> 5;
    int wm   = (wid & 1) * 64;
    int wn   = (wid >> 1) * 32;

    uint32_t soff[4];
    const __nv_bfloat16* gsrc[4];
#pragma unroll
    for (int u = 0; u < 4; u++) {
        int q = t + u * 256;
        if (q < 512) {
            int plane = q >> 8, ca = q & 255;
            int row = ca >> 1, hf = ca & 1;
            gsrc[u] = (plane ? Al : Ah) + (long long)(i0 + row) * lda + hf * 8;
            soff[u] = plane * 4096 + (uint32_t)((ca ^ ((ca >> 3) & 1)) * 16);
        } else {
            int q2 = q - 512;
            int plane = q2 >> 8, cb = q2 & 255;
            int row = cb >> 1, hf = cb & 1;
            gsrc[u] = (plane ? Bl : Bh) + (long long)(j0 + row) * ldb + hf * 8;
            soff[u] = 8192 + plane * 4096 + (uint32_t)((cb ^ ((cb >> 3) & 1)) * 16);
        }
    }

#define ISSUE8(cc)                                                            \
    do {                                                                      \
        uint32_t base_ = sb0 + (uint32_t)(((cc) & 3) * STG128);               \
        int k_ = ks + (cc) * 16;                                              \
        _Pragma("unroll")                                                     \
        for (int u = 0; u < 4; u++)                                           \
            asm volatile("cp.async.ca.shared.global [%0], [%1], 16;"          \
                         :: "r"(base_ + soff[u]), "l"(gsrc[u] + k_) : "memory"); \
    } while (0)

    uint32_t addrA[4][2], addrB[2][2];
#pragma unroll
    for (int mt = 0; mt < 4; mt++) {
        int row = wm + mt * 16 + (lane & 15);
        int hf = lane >> 4;
        int ca = row * 2 + hf;
        uint32_t ph = (uint32_t)((ca ^ ((ca >> 3) & 1)) * 16);
#pragma unroll
        for (int pl = 0; pl < 2; pl++) addrA[mt][pl] = sb0 + pl * 4096 + ph;
    }
#pragma unroll
    for (int ng = 0; ng < 2; ng++) {
        int n = wn + ng * 16 + ((lane >> 4) & 1) * 8 + (lane & 7);
        int hf = (lane >> 3) & 1;
        int cb = n * 2 + hf;
        uint32_t ph = (uint32_t)((cb ^ ((cb >> 3) & 1)) * 16);
#pragma unroll
        for (int pl = 0; pl < 2; pl++) addrB[ng][pl] = sb0 + 8192 + pl * 4096 + ph;
    }

#pragma unroll
    for (int s = 0; s < 3; s++) {
        if (s < KC) ISSUE8(s);
        asm volatile("cp.async.commit_group;" ::: "memory");
    }

    float acc[4][4][4];
#pragma unroll
    for (int mt = 0; mt < 4; mt++)
#pragma unroll
        for (int nt = 0; nt < 4; nt++)
#pragma unroll
            for (int e = 0; e < 4; e++) acc[mt][nt][e] = 0.0f;

    for (int c = 0; c < KC; c++) {
        asm volatile("cp.async.wait_group 2;" ::: "memory");
        __syncthreads();
        {
            int s = c + 3;
            if (s < KC) ISSUE8(s);
            asm volatile("cp.async.commit_group;" ::: "memory");
        }
        uint32_t st = (uint32_t)((c & 3) * STG128);

        uint32_t ah[4][4], bb[2][4];
        ldsm4(ah[0], addrA[0][0] + st);
        ldsm4(ah[1], addrA[1][0] + st);
        ldsm4(ah[2], addrA[2][0] + st);
        ldsm4(ah[3], addrA[3][0] + st);
        ldsm4(bb[0], addrB[0][0] + st);
        ldsm4(bb[1], addrB[1][0] + st);
        // hh
#pragma unroll
        for (int mt = 0; mt < 4; mt++)
#pragma unroll
            for (int nt = 0; nt < 4; nt++)
                mma_bf16(acc[mt][nt], ah[mt], &bb[nt >> 1][(nt & 1) * 2]);
        // lh
        {
            uint32_t al[4][4];
            ldsm4(al[0], addrA[0][1] + st);
            ldsm4(al[1], addrA[1][1] + st);
            ldsm4(al[2], addrA[2][1] + st);
            ldsm4(al[3], addrA[3][1] + st);
#pragma unroll
            for (int mt = 0; mt < 4; mt++)
#pragma unroll
                for (int nt = 0; nt < 4; nt++)
                    mma_bf16(acc[mt][nt], al[mt], &bb[nt >> 1][(nt & 1) * 2]);
        }
        // hl
        ldsm4(bb[0], addrB[0][1] + st);
        ldsm4(bb[1], addrB[1][1] + st);
#pragma unroll
        for (int mt = 0; mt < 4; mt++)
#pragma unroll
            for (int nt = 0; nt < 4; nt++)
                mma_bf16(acc[mt][nt], ah[mt], &bb[nt >> 1][(nt & 1) * 2]);
    }
#undef ISSUE8

    int gid = lane >> 2, tig = lane & 3;
#pragma unroll
    for (int mt = 0; mt < 4; mt++) {
        int r = i0 + wm + mt * 16 + gid;
#pragma unroll
        for (int nt = 0; nt < 4; nt++) {
            int cc = j0 + wn + nt * 8 + tig * 2;
            C[(long long)r * ldc + cc]           = acc[mt][nt][0];
            C[(long long)r * ldc + cc + 1]       = acc[mt][nt][1];
            C[(long long)(r + 8) * ldc + cc]     = acc[mt][nt][2];
            C[(long long)(r + 8) * ldc + cc + 1] = acc[mt][nt][3];
        }
    }
}

// ---- qkv split: sums 2 split-K partials, l2norm, plane emission, kv out ----
__global__ void qkv_split_kernel(const float* __restrict__ qkv0,
                                 const float* __restrict__ qkv1,
                                 const float* __restrict__ tptr,
                                 float* __restrict__ kv_out)
{
    int n2 = blockIdx.x, h = blockIdx.y;
    int t = threadIdx.x;
    int sub = t >> 6, d = t & 63;
    int n = n2 * 2 + sub;
    long long off = (long long)n * 3072 + h * 192 + d * 3;
    const float* b0 = qkv0 + off;
    const float* b1 = qkv1 + off;
    float q = b0[0] + b1[0], k = b0[1] + b1[1], v = b0[2] + b1[2];

    float sq = q * q, sk = k * k;
#pragma unroll
    for (int o = 16; o; o >>= 1) {
        sq += __shfl_down_sync(0xffffffffu, sq, o);
        sk += __shfl_down_sync(0xffffffffu, sk, o);
    }
    __shared__ float sh[4][2];
    __shared__ float vsh[64];
    int w = t >> 5;
    if ((t & 31) == 0) { sh[w][0] = sq; sh[w][1] = sk; }
    if (sub == 1) vsh[d] = v;
    __syncthreads();
    int wb = sub * 2;
    float nq = sqrtf(sh[wb][0] + sh[wb + 1][0]);
    float nk = sqrtf(sh[wb][1] + sh[wb + 1][1]);
    float temp = tptr[0];
    float qv = q / fmaxf(nq, 1e-12f) * temp;
    float kv = k / fmaxf(nk, 1e-12f);

    int idx = (h * NTOK + n) * HDIM + d;
    kv_out[idx] = k;
    kv_out[NHEAD * NTOK * HDIM + idx] = v;

    float qnb = __shfl_down_sync(0xffffffffu, qv, 1);
    float knb = __shfl_down_sync(0xffffffffu, kv, 1);
    if ((d & 1) == 0) {
        int pi = (h * NTOK + n) * 32 + (d >> 1);
        uint2 pq = pack2_bf16(qv, qnb);
        uint2 pk = pack2_bf16(kv, knb);
        ((uint32_t*)g_qnh)[pi] = pq.x; ((uint32_t*)g_qnl)[pi] = pq.y;
        ((uint32_t*)g_knh)[pi] = pk.x; ((uint32_t*)g_knl)[pi] = pk.y;
    }
    if (sub == 0) {
        int pi = (h * HDIM + d) * 1024 + n2;
        uint2 pv = pack2_bf16(v, vsh[d]);
        ((uint32_t*)g_vth)[pi] = pv.x; ((uint32_t*)g_vtl)[pi] = pv.y;
    }
}

// ---------- talking-heads pre mix + pos_bias (R9 measured form) -------------
__global__ void __launch_bounds__(256, 3)
mix_pre_kernel(const float* __restrict__ S0,
               const float* __restrict__ Wpre,
               const float* __restrict__ bpre,
               const float* __restrict__ pb,
               float* __restrict__ s)
{
    int j0 = blockIdx.x * 64, i0 = blockIdx.y * 64;
    if (j0 > i0 + 63) return;
    __shared__ float w[16][16];
    __shared__ float bp[16];
    int t = threadIdx.x;
    w[t >> 4][t & 15] = Wpre[t];
    if (t < 16) bp[t] = bpre[t];
    __syncthreads();

    int tj = t & 63, ti = t >> 6;
    for (int r = 0; r < 16; r++) {
        int i = i0 + (r << 2) + ti;
        int j = j0 + tj;
        if (j > i) continue;
        long long cell = (long long)i * NTOK + j;
        float acc[16];
#pragma unroll
        for (int g = 0; g < 16; g++) acc[g] = bp[g];
#pragma unroll
        for (int h = 0; h < 16; h++) {
            float v = __ldg(S0 + (long long)h * NN + cell);
#pragma unroll
            for (int g = 0; g < 16; g++) acc[g] = fmaf(w[g][h], v, acc[g]);
        }
#pragma unroll
        for (int g = 0; g < 16; g++)
            s[(long long)g * NN + cell] = acc[g] + __ldg(pb + (long long)g * NN + cell);
    }
}

// ---------- per-row softmax stats (causal), single pass ---------------------
__global__ void rowstats_kernel(const float* __restrict__ s,
                                float* __restrict__ m_out, float* __restrict__ invl_out)
{
    int i = blockIdx.x, g = blockIdx.y;
    int len = i + 1;
    const float* row = s + (long long)g * NN + (long long)i * NTOK;
    int t = threadIdx.x;

    float x[8];
#pragma unroll
    for (int b = 0; b < 2; b++) {
        int j0 = t * 4 + b * 1024;
        if (j0 + 3 < len) {
            float4 v = *(const float4*)(row + j0);
            x[b*4+0] = v.x; x[b*4+1] = v.y; x[b*4+2] = v.z; x[b*4+3] = v.w;
        } else {
#pragma unroll
            for (int u = 0; u < 4; u++) {
                int j = j0 + u;
                x[b*4+u] = (j < len) ? row[j] : -3.4e38f;
            }
        }
    }
    float m = -3.4e38f;
#pragma unroll
    for (int u = 0; u < 8; u++) m = fmaxf(m, x[u]);
    float ssum = 0.0f;
#pragma unroll
    for (int u = 0; u < 8; u++) ssum += fexp(x[u] - m);

    __shared__ float rm[256], rs[256];
    rm[t] = m; rs[t] = ssum;
    __syncthreads();
    for (int o = 128; o; o >>= 1) {
        if (t < o) {
            float m1 = rm[t], m2 = rm[t + o];
            float M = fmaxf(m1, m2);
            rs[t] = rs[t] * fexp(m1 - M) + rs[t + o] * fexp(m2 - M);
            rm[t] = M;
        }
        __syncthreads();
    }
    if (t == 0) {
        m_out[g * NTOK + i] = rm[0];
        invl_out[g * NTOK + i] = 1.0f / rs[0];
    }
}

// ---- softmax + post-mix, emits Pm hi/lo planes -----------------------------
__global__ void __launch_bounds__(256, 3)
softmax_mix_kernel(const float* __restrict__ s,
                   const float* __restrict__ m_arr,
                   const float* __restrict__ invl_arr,
                   const float* __restrict__ Wpost,
                   const float* __restrict__ bpost,
                   uint32_t* __restrict__ PmH, uint32_t* __restrict__ PmL)
{
    int j0 = blockIdx.x * 64, i0 = blockIdx.y * 64;
    if (j0 > i0 + 127) return;
    __shared__ float w[16][16];
    __shared__ float bp[16];
    __shared__ float sm[16][64];
    __shared__ float sil[16][64];
    int t = threadIdx.x;
    w[t >> 4][t & 15] = Wpost[t];
    if (t < 16) bp[t] = bpost[t];
#pragma unroll
    for (int e = 0; e < 4; e++) {
        int id = t + e * 256;
        int h = id >> 6, ir = id & 63;
        sm[h][ir]  = m_arr[h * NTOK + i0 + ir];
        sil[h][ir] = invl_arr[h * NTOK + i0 + ir];
    }
    __syncthreads();

    int tj2 = t & 31;
    int ti  = t >> 5;
    int j = j0 + tj2 * 2;
#pragma unroll
    for (int r = 0; r < 8; r++) {
        int ir = r * 8 + ti;
        int i = i0 + ir;
        bool v0 = (j <= i), v1 = (j + 1 <= i);
        float a0[16], a1[16];
#pragma unroll
        for (int g = 0; g < 16; g++) {
            a0[g] = v0 ? bp[g] : 0.0f;
            a1[g] = v1 ? bp[g] : 0.0f;
        }
        if (v0) {
            long long cell = (long long)i * NTOK + j;
#pragma unroll
            for (int h = 0; h < 16; h++) {
                float2 sv = *(const float2*)(s + (long long)h * NN + cell);
                float il = sil[h][ir], mm = sm[h][ir];
                float e0 = fexp(sv.x - mm) * il;
                float e1 = v1 ? fexp(sv.y - mm) * il : 0.0f;
#pragma unroll
                for (int g = 0; g < 16; g++) {
                    a0[g] = fmaf(w[g][h], e0, a0[g]);
                    a1[g] = fmaf(w[g][h], e1, a1[g]);
                }
            }
        }
        long long pidx = (long long)i * 1024 + tj2 + (j0 >> 1);
#pragma unroll
        for (int g = 0; g < 16; g++) {
            uint2 pk = pack2_bf16(a0[g], a1[g]);
            PmH[(long long)g * (NN / 2) + pidx] = pk.x;
            PmL[(long long)g * (NN / 2) + pidx] = pk.y;
        }
    }
}

// ---------------------------------------------------------------------------
extern "C" void kernel_launch(void* const* d_in, const int* in_sizes, int n_in,
                              void* d_out, int out_size)
{
    const float* x     = (const float*)d_in[0];
    const float* pb    = (const float*)d_in[1];
    const float* Wqkv  = (const float*)d_in[3];
    const float* Wout  = (const float*)d_in[4];
    const float* temp  = (const float*)d_in[5];
    const float* Wpre  = (const float*)d_in[6];
    const float* bpre  = (const float*)d_in[7];
    const float* Wpost = (const float*)d_in[8];
    const float* bpost = (const float*)d_in[9];
    float* out = (float*)d_out;
    float* kv_out = out + NTOK * CDIM;

    float *qkv0_p, *qkv1_p, *bufA_p, *bufB_p, *m_p, *invl_p, *o2pp, *outp;
    cudaGetSymbolAddress((void**)&qkv0_p, g_qkv0);
    cudaGetSymbolAddress((void**)&qkv1_p, g_qkv1);
    cudaGetSymbolAddress((void**)&bufA_p, g_bufA);
    cudaGetSymbolAddress((void**)&bufB_p, g_bufB);
    cudaGetSymbolAddress((void**)&m_p, g_m);
    cudaGetSymbolAddress((void**)&invl_p, g_invl);
    cudaGetSymbolAddress((void**)&o2pp, g_o2p);
    cudaGetSymbolAddress((void**)&outp, g_outp);

    __nv_bfloat16 *xh, *xl, *wqh, *wql, *woh, *wol, *qnh, *qnl, *knh, *knl,
                  *vth, *vtl, *o2h, *o2l;
    cudaGetSymbolAddress((void**)&xh, g_xh);
    cudaGetSymbolAddress((void**)&xl, g_xl);
    cudaGetSymbolAddress((void**)&wqh, g_wqh);
    cudaGetSymbolAddress((void**)&wql, g_wql);
    cudaGetSymbolAddress((void**)&woh, g_woh);
    cudaGetSymbolAddress((void**)&wol, g_wol);
    cudaGetSymbolAddress((void**)&qnh, g_qnh);
    cudaGetSymbolAddress((void**)&qnl, g_qnl);
    cudaGetSymbolAddress((void**)&knh, g_knh);
    cudaGetSymbolAddress((void**)&knl, g_knl);
    cudaGetSymbolAddress((void**)&vth, g_vth);
    cudaGetSymbolAddress((void**)&vtl, g_vtl);
    cudaGetSymbolAddress((void**)&o2h, g_o2h);
    cudaGetSymbolAddress((void**)&o2l, g_o2l);

    cudaFuncSetAttribute(gemm_lm, cudaFuncAttributeMaxDynamicSharedMemorySize,
                         (int)GEMM_SMEM);
    cudaFuncSetAttribute(gemm_lm128, cudaFuncAttributeMaxDynamicSharedMemorySize,
                         (int)GEMM128_SMEM);

    const long long PSZ = 2048LL * 1024;
    const long long QSZ = 2048LL * 3072;

    // 0) pack fp32 inputs into hi/lo planes
    pack_planes<<<2048, 256>>>(x, xh, xl, 2048 * 1024);
    pack_planes<<<3072, 256>>>(Wqkv, wqh, wql, 3072 * 1024);
    pack_planes<<<1024, 256>>>(Wout, woh, wol, 1024 * 1024);

    // 1) qkv = x @ Wqkv^T : split-K x2 fp32 partials (128x128 tiles)
    gemm_lm128<<<dim3(24, 16, 2), 256, GEMM128_SMEM>>>(
        xh, xl, wqh, wql, qkv0_p, 1024, 1024, 1024, 3072,
        (long long)(qkv1_p - qkv0_p), 1);

    // 2) split (sums partials) + l2norm + qn/kn/vT planes + kv output
    qkv_split_kernel<<<dim3(1024, NHEAD), 128>>>(qkv0_p, qkv1_p, temp, kv_out);

    // 3) S0[h] = qn[h] @ kn[h]^T (causal tiles only) -> bufA fp32
    gemm_lm<<<dim3(32, 16, NHEAD), 256, GEMM_SMEM>>>(
        qnh, qnl, knh, knl, bufA_p, 64, 64, 64, 2048,
        (long long)NTOK * HDIM, (long long)NTOK * HDIM, (long long)NN, 0, 1);

    // 4) pre talking-heads mix + pos_bias -> s
    mix_pre_kernel<<<dim3(32, 32), 256>>>(bufA_p, Wpre, bpre, pb, bufB_p);

    // 5) per-row max / inv-sum-exp
    rowstats_kernel<<<dim3(NTOK, NHEAD), 256>>>(bufB_p, m_p, invl_p);

    // 6) softmax + post-mix -> Pm hi/lo planes (reuses bufA bytes)
    uint32_t* PmH = (uint32_t*)bufA_p;
    uint32_t* PmL = PmH + (long long)NHEAD * NN / 2;
    softmax_mix_kernel<<<dim3(32, 32), 256>>>(
        bufB_p, m_p, invl_p, Wpost, bpost, PmH, PmL);

    // 7) PV split-K x4: o2part[part] = Pm @ v
    const __nv_bfloat16* PmHb = (const __nv_bfloat16*)PmH;
    const __nv_bfloat16* PmLb = (const __nv_bfloat16*)PmL;
    gemm_lm<<<dim3(1, 16, NHEAD * 4), 256, GEMM_SMEM>>>(
        PmHb, PmLb, vth, vtl, o2pp, 2048, 2048, 2048, 1024,
        (long long)NN, (long long)HDIM * NTOK, 64, PSZ, 2);

    // 8) combine partials -> o2 planes
    combine_pack4<<<2048, 256>>>(o2pp, o2pp + PSZ, o2pp + 2 * PSZ, o2pp + 3 * PSZ,
                                 o2h, o2l, 2048 * 1024);

    // 9) out = o2 @ Wout^T (split-K x4, fp32 partials)
    gemm_lm<<<dim3(16, 16, 4), 256, GEMM_SMEM>>>(
        o2h, o2l, woh, wol, outp, 1024, 1024, 1024, 1024,
        0, 0, 0, PSZ, 3);

    // 10) combine out partials
    combine_out4<<<2048, 256>>>(outp, outp + PSZ, outp + 2 * PSZ, outp + 3 * PSZ,
                                out, 2048 * 1024);
}

// round 15
// speedup vs baseline: 1.1236x; 1.1236x over previous
#include <cuda_runtime.h>
#include <cuda_bf16.h>
#include <cuda_fp16.h>
#include <cstdint>

// ---------------------------------------------------------------------------
// transformer_75419625718098: talking-heads causal attention
// B=1, N=2048, C=1024, H=16, D=64
// Round 15: split-fp16 2-MMA GEMMs (hh + lh; B fp16-rounded, A hi+lo).
// MMA work -33%, B staging/LDSM eliminated. qkv split-K reverted (R14 neutral).
// ---------------------------------------------------------------------------

#define NTOK 2048
#define NHEAD 16
#define HDIM 64
#define CDIM 1024
#define NN (2048*2048)

// 64-wide gemm: stage = Ahi 4K + Alo 4K + Bhi 2K
#define STG_BYTES 10240
#define GEMM_SMEM (4 * STG_BYTES)          // 40960
// 128-wide gemm (qkv): stage = Ahi 4K + Alo 4K + Bhi 4K
#define STG128 12288
#define GEMM128_SMEM (4 * STG128)          // 49152

// ------------------------- device scratch ----------------------------------
__device__ float g_qkv[2048 * 3072];
__device__ float g_bufA[(long long)NHEAD * NN]; // S0 fp32 -> Pm hi/lo planes
__device__ float g_bufB[(long long)NHEAD * NN]; // s (mixed logits)
__device__ float g_m   [NHEAD * NTOK];
__device__ float g_invl[NHEAD * NTOK];
__device__ float g_o2p [4LL * 2048 * 1024];     // PV split-K partials (x4)
__device__ float g_outp[4LL * 2048 * 1024];     // out-proj split-K partials (x4)
// (hi,lo) fp16 planes (lo only needed for A-side operands)
__device__ __half g_xh [2048 * 1024], g_xl [2048 * 1024];
__device__ __half g_wqh[3072 * 1024], g_wql[3072 * 1024];
__device__ __half g_woh[1024 * 1024], g_wol[1024 * 1024];
__device__ __half g_qnh[NHEAD * NTOK * HDIM], g_qnl[NHEAD * NTOK * HDIM];
__device__ __half g_knh[NHEAD * NTOK * HDIM];
__device__ __half g_vth[NHEAD * HDIM * NTOK];
__device__ __half g_o2h[2048 * 1024], g_o2l[2048 * 1024];

// fast exp on the FMA pipe
__device__ __forceinline__ float fexp(float x) {
    float t = fmaxf(x * 1.4426950408889634f, -126.0f);
    int ei = __float2int_rd(t);
    float f = t - (float)ei;
    float y = 0.69314718055994531f * f;
    float p = fmaf(y, 1.3888889e-3f, 8.3333333e-3f);
    p = fmaf(y, p, 4.1666667e-2f);
    p = fmaf(y, p, 1.6666667e-1f);
    p = fmaf(y, p, 0.5f);
    p = fmaf(y, p, 1.0f);
    p = fmaf(y, p, 1.0f);
    return p * __int_as_float((ei + 127) << 23);
}

// (x0,x1) -> (hi_f16x2, lo_f16x2)
__device__ __forceinline__ uint2 pack2_f16(float x0, float x1) {
    __half2 h2 = __floats2half2_rn(x0, x1);
    float2 hf = __half22float2(h2);
    __half2 l2 = __floats2half2_rn(x0 - hf.x, x1 - hf.y);
    uint2 r;
    r.x = *reinterpret_cast<uint32_t*>(&h2);
    r.y = *reinterpret_cast<uint32_t*>(&l2);
    return r;
}

__device__ __forceinline__ void mma_f16(float* c, const uint32_t* a, const uint32_t* b) {
    asm volatile(
        "mma.sync.aligned.m16n8k16.row.col.f32.f16.f16.f32 "
        "{%0,%1,%2,%3},{%4,%5,%6,%7},{%8,%9},{%0,%1,%2,%3};"
        : "+f"(c[0]), "+f"(c[1]), "+f"(c[2]), "+f"(c[3])
        : "r"(a[0]), "r"(a[1]), "r"(a[2]), "r"(a[3]), "r"(b[0]), "r"(b[1]));
}

__device__ __forceinline__ void ldsm4(uint32_t* r, uint32_t addr) {
    asm volatile("ldmatrix.sync.aligned.m8n8.x4.shared.b16 {%0,%1,%2,%3}, [%4];"
                 : "=r"(r[0]), "=r"(r[1]), "=r"(r[2]), "=r"(r[3]) : "r"(addr));
}

// ---------------- pack fp32 -> hi/lo fp16 planes ----------------------------
__global__ void pack_planes(const float* __restrict__ s,
                            __half* __restrict__ hi,
                            __half* __restrict__ lo, int n)
{
    int i = (blockIdx.x * 256 + threadIdx.x) * 4;
    if (i >= n) return;
    float4 v = *(const float4*)(s + i);
    uint2 p01 = pack2_f16(v.x, v.y);
    uint2 p23 = pack2_f16(v.z, v.w);
    *(uint2*)(hi + i) = make_uint2(p01.x, p23.x);
    *(uint2*)(lo + i) = make_uint2(p01.y, p23.y);
}

// ------------- combine 4 split-K partials + pack to planes ------------------
__global__ void combine_pack4(const float* __restrict__ p0, const float* __restrict__ p1,
                              const float* __restrict__ p2, const float* __restrict__ p3,
                              __half* __restrict__ hi, __half* __restrict__ lo, int n)
{
    int i = (blockIdx.x * 256 + threadIdx.x) * 4;
    if (i >= n) return;
    float4 a = *(const float4*)(p0 + i);
    float4 b = *(const float4*)(p1 + i);
    float4 c = *(const float4*)(p2 + i);
    float4 d = *(const float4*)(p3 + i);
    uint2 p01 = pack2_f16(a.x + b.x + c.x + d.x, a.y + b.y + c.y + d.y);
    uint2 p23 = pack2_f16(a.z + b.z + c.z + d.z, a.w + b.w + c.w + d.w);
    *(uint2*)(hi + i) = make_uint2(p01.x, p23.x);
    *(uint2*)(lo + i) = make_uint2(p01.y, p23.y);
}

// ------------- combine 4 split-K partials (fp32 out) ------------------------
__global__ void combine_out4(const float* __restrict__ p0, const float* __restrict__ p1,
                             const float* __restrict__ p2, const float* __restrict__ p3,
                             float* __restrict__ o, int n)
{
    int i = (blockIdx.x * 256 + threadIdx.x) * 4;
    if (i >= n) return;
    float4 a = *(const float4*)(p0 + i);
    float4 b = *(const float4*)(p1 + i);
    float4 c = *(const float4*)(p2 + i);
    float4 d = *(const float4*)(p3 + i);
    *(float4*)(o + i) = make_float4(a.x + b.x + c.x + d.x, a.y + b.y + c.y + d.y,
                                    a.z + b.z + c.z + d.z, a.w + b.w + c.w + d.w);
}

// ---------- split-fp16 2-MMA GEMM (128x64): C = A*B^T -----------------------
// A planes hi+lo [M][K], B hi only [N][K].
// mode 0: plain batched. mode 1: causal skip (QK).
// mode 2: causal split-K x4 PV (z = 4*g+part). mode 3: plain split-K x4.
__global__ void __launch_bounds__(256, 3)
gemm_lm(const __half* __restrict__ Ah, const __half* __restrict__ Al,
        const __half* __restrict__ Bh,
        float* __restrict__ C,
        int K, int lda, int ldb, int ldc,
        long long sA, long long sB, long long sC, long long ssplit, int mode)
{
    int j0 = blockIdx.x * 64;
    int i0 = blockIdx.y * 128;
    if (mode == 1 && j0 > i0 + 127) return;
    int bz = blockIdx.z;
    int g, part;
    if (mode == 2)      { g = bz >> 2; part = bz & 3; }
    else if (mode == 3) { g = 0;       part = bz;     }
    else                { g = bz;      part = 0;      }
    Ah += (long long)g * sA; Al += (long long)g * sA;
    Bh += (long long)g * sB;
    C  += (long long)g * sC + (long long)part * ssplit;

    int ks = 0, ke = K;
    if (mode == 2) {
        int Keff = min(K, i0 + 128);
        int q1 = (Keff >> 2) & ~15;
        int q2 = (Keff >> 1) & ~15;
        int q3 = ((3 * Keff) >> 2) & ~15;
        ks = (part == 0) ? 0  : (part == 1) ? q1 : (part == 2) ? q2 : q3;
        ke = (part == 0) ? q1 : (part == 1) ? q2 : (part == 2) ? q3 : Keff;
    } else if (mode == 3) {
        int quarter = K >> 2;
        ks = part * quarter;
        ke = ks + quarter;
    }
    int KC = (ke - ks) >> 4;

    extern __shared__ char smem[];
    uint32_t sb0 = (uint32_t)__cvta_generic_to_shared(smem);

    int t = threadIdx.x;
    int lane = t & 31;
    int wid  = t >> 5;
    int wm   = (wid & 3) * 32;
    int wn   = (wid >> 2) * 32;

    // staging: Ahi 256 chunks, Alo 256 chunks (1 each per thread),
    // Bhi 128 chunks (threads 0..127)
    int arow = t >> 1, ahf = t & 1;
    const __half* gA0 = Ah + (long long)(i0 + arow) * lda + ahf * 8;
    const __half* gA1 = Al + (long long)(i0 + arow) * lda + ahf * 8;
    uint32_t aoff = (uint32_t)((t ^ ((t >> 3) & 1)) * 16);
    bool hasB = (t < 128);
    int brow = t >> 1, bhf = t & 1;
    const __half* gB = Bh + (long long)(j0 + brow) * ldb + bhf * 8;
    uint32_t boff = 8192 + (uint32_t)((t ^ ((t >> 3) & 1)) * 16);

#define ISSUE(cc)                                                             \
    do {                                                                      \
        uint32_t base_ = sb0 + (uint32_t)(((cc) & 3) * STG_BYTES);            \
        int k_ = ks + (cc) * 16;                                              \
        asm volatile("cp.async.ca.shared.global [%0], [%1], 16;"              \
                     :: "r"(base_ + aoff), "l"(gA0 + k_) : "memory");         \
        asm volatile("cp.async.ca.shared.global [%0], [%1], 16;"              \
                     :: "r"(base_ + 4096 + aoff), "l"(gA1 + k_) : "memory");  \
        if (hasB)                                                             \
            asm volatile("cp.async.ca.shared.global [%0], [%1], 16;"          \
                         :: "r"(base_ + boff), "l"(gB + k_) : "memory");      \
    } while (0)

    uint32_t addrA[2][2], addrB[2];
#pragma unroll
    for (int mt = 0; mt < 2; mt++) {
        int row = wm + mt * 16 + (lane & 15);
        int hf = lane >> 4;
        int ca = row * 2 + hf;
        uint32_t ph = (uint32_t)((ca ^ ((ca >> 3) & 1)) * 16);
        addrA[mt][0] = sb0 + ph;
        addrA[mt][1] = sb0 + 4096 + ph;
    }
#pragma unroll
    for (int ng = 0; ng < 2; ng++) {
        int n = wn + ng * 16 + ((lane >> 4) & 1) * 8 + (lane & 7);
        int hf = (lane >> 3) & 1;
        int cb = n * 2 + hf;
        uint32_t ph = (uint32_t)((cb ^ ((cb >> 3) & 1)) * 16);
        addrB[ng] = sb0 + 8192 + ph;
    }

#pragma unroll
    for (int s = 0; s < 3; s++) {
        if (s < KC) ISSUE(s);
        asm volatile("cp.async.commit_group;" ::: "memory");
    }

    float acc[2][4][4];
#pragma unroll
    for (int mt = 0; mt < 2; mt++)
#pragma unroll
        for (int nt = 0; nt < 4; nt++)
#pragma unroll
            for (int e = 0; e < 4; e++) acc[mt][nt][e] = 0.0f;

    for (int c = 0; c < KC; c++) {
        asm volatile("cp.async.wait_group 2;" ::: "memory");
        __syncthreads();
        {
            int s = c + 3;
            if (s < KC) ISSUE(s);
            asm volatile("cp.async.commit_group;" ::: "memory");
        }
        uint32_t st = (uint32_t)((c & 3) * STG_BYTES);

        uint32_t ah[2][4], al[2][4], bb[2][4];
        ldsm4(ah[0], addrA[0][0] + st);
        ldsm4(ah[1], addrA[1][0] + st);
        ldsm4(al[0], addrA[0][1] + st);
        ldsm4(al[1], addrA[1][1] + st);
        ldsm4(bb[0], addrB[0] + st);
        ldsm4(bb[1], addrB[1] + st);
#pragma unroll
        for (int mt = 0; mt < 2; mt++)
#pragma unroll
            for (int nt = 0; nt < 4; nt++)
                mma_f16(acc[mt][nt], ah[mt], &bb[nt >> 1][(nt & 1) * 2]);
#pragma unroll
        for (int mt = 0; mt < 2; mt++)
#pragma unroll
            for (int nt = 0; nt < 4; nt++)
                mma_f16(acc[mt][nt], al[mt], &bb[nt >> 1][(nt & 1) * 2]);
    }
#undef ISSUE

    int gid = lane >> 2, tig = lane & 3;
#pragma unroll
    for (int mt = 0; mt < 2; mt++) {
        int r = i0 + wm + mt * 16 + gid;
#pragma unroll
        for (int nt = 0; nt < 4; nt++) {
            int cc = j0 + wn + nt * 8 + tig * 2;
            C[(long long)r * ldc + cc]           = acc[mt][nt][0];
            C[(long long)r * ldc + cc + 1]       = acc[mt][nt][1];
            C[(long long)(r + 8) * ldc + cc]     = acc[mt][nt][2];
            C[(long long)(r + 8) * ldc + cc + 1] = acc[mt][nt][3];
        }
    }
}

// ---------- split-fp16 2-MMA GEMM (128x128): C = A*B^T (qkv) ----------------
__global__ void __launch_bounds__(256, 2)
gemm_lm128(const __half* __restrict__ Ah, const __half* __restrict__ Al,
           const __half* __restrict__ Bh,
           float* __restrict__ C, int K, int lda, int ldb, int ldc)
{
    int j0 = blockIdx.x * 128;
    int i0 = blockIdx.y * 128;
    int KC = K >> 4;

    extern __shared__ char smem[];
    uint32_t sb0 = (uint32_t)__cvta_generic_to_shared(smem);

    int t = threadIdx.x;
    int lane = t & 31;
    int wid  = t >> 5;
    int wm   = (wid & 1) * 64;
    int wn   = (wid >> 1) * 32;

    // staging: 3 chunks per thread (Ahi, Alo, Bhi; 256 chunks each)
    int arow = t >> 1, ahf = t & 1;
    const __half* gA0 = Ah + (long long)(i0 + arow) * lda + ahf * 8;
    const __half* gA1 = Al + (long long)(i0 + arow) * lda + ahf * 8;
    const __half* gB  = Bh + (long long)(j0 + arow) * ldb + ahf * 8;
    uint32_t coff = (uint32_t)((t ^ ((t >> 3) & 1)) * 16);

#define ISSUE8(cc)                                                            \
    do {                                                                      \
        uint32_t base_ = sb0 + (uint32_t)(((cc) & 3) * STG128);               \
        int k_ = (cc) * 16;                                                   \
        asm volatile("cp.async.ca.shared.global [%0], [%1], 16;"              \
                     :: "r"(base_ + coff), "l"(gA0 + k_) : "memory");         \
        asm volatile("cp.async.ca.shared.global [%0], [%1], 16;"              \
                     :: "r"(base_ + 4096 + coff), "l"(gA1 + k_) : "memory");  \
        asm volatile("cp.async.ca.shared.global [%0], [%1], 16;"              \
                     :: "r"(base_ + 8192 + coff), "l"(gB + k_) : "memory");   \
    } while (0)

    uint32_t addrA[4][2], addrB[2];
#pragma unroll
    for (int mt = 0; mt < 4; mt++) {
        int row = wm + mt * 16 + (lane & 15);
        int hf = lane >> 4;
        int ca = row * 2 + hf;
        uint32_t ph = (uint32_t)((ca ^ ((ca >> 3) & 1)) * 16);
        addrA[mt][0] = sb0 + ph;
        addrA[mt][1] = sb0 + 4096 + ph;
    }
#pragma unroll
    for (int ng = 0; ng < 2; ng++) {
        int n = wn + ng * 16 + ((lane >> 4) & 1) * 8 + (lane & 7);
        int hf = (lane >> 3) & 1;
        int cb = n * 2 + hf;
        uint32_t ph = (uint32_t)((cb ^ ((cb >> 3) & 1)) * 16);
        addrB[ng] = sb0 + 8192 + ph;
    }

#pragma unroll
    for (int s = 0; s < 3; s++) {
        if (s < KC) ISSUE8(s);
        asm volatile("cp.async.commit_group;" ::: "memory");
    }

    float acc[4][4][4];
#pragma unroll
    for (int mt = 0; mt < 4; mt++)
#pragma unroll
        for (int nt = 0; nt < 4; nt++)
#pragma unroll
            for (int e = 0; e < 4; e++) acc[mt][nt][e] = 0.0f;

    for (int c = 0; c < KC; c++) {
        asm volatile("cp.async.wait_group 2;" ::: "memory");
        __syncthreads();
        {
            int s = c + 3;
            if (s < KC) ISSUE8(s);
            asm volatile("cp.async.commit_group;" ::: "memory");
        }
        uint32_t st = (uint32_t)((c & 3) * STG128);

        uint32_t ah[4][4], bb[2][4];
        ldsm4(ah[0], addrA[0][0] + st);
        ldsm4(ah[1], addrA[1][0] + st);
        ldsm4(ah[2], addrA[2][0] + st);
        ldsm4(ah[3], addrA[3][0] + st);
        ldsm4(bb[0], addrB[0] + st);
        ldsm4(bb[1], addrB[1] + st);
        // hh
#pragma unroll
        for (int mt = 0; mt < 4; mt++)
#pragma unroll
            for (int nt = 0; nt < 4; nt++)
                mma_f16(acc[mt][nt], ah[mt], &bb[nt >> 1][(nt & 1) * 2]);
        // lh
        {
            uint32_t al[4][4];
            ldsm4(al[0], addrA[0][1] + st);
            ldsm4(al[1], addrA[1][1] + st);
            ldsm4(al[2], addrA[2][1] + st);
            ldsm4(al[3], addrA[3][1] + st);
#pragma unroll
            for (int mt = 0; mt < 4; mt++)
#pragma unroll
                for (int nt = 0; nt < 4; nt++)
                    mma_f16(acc[mt][nt], al[mt], &bb[nt >> 1][(nt & 1) * 2]);
        }
    }
#undef ISSUE8

    int gid = lane >> 2, tig = lane & 3;
#pragma unroll
    for (int mt = 0; mt < 4; mt++) {
        int r = i0 + wm + mt * 16 + gid;
#pragma unroll
        for (int nt = 0; nt < 4; nt++) {
            int cc = j0 + wn + nt * 8 + tig * 2;
            C[(long long)r * ldc + cc]           = acc[mt][nt][0];
            C[(long long)r * ldc + cc + 1]       = acc[mt][nt][1];
            C[(long long)(r + 8) * ldc + cc]     = acc[mt][nt][2];
            C[(long long)(r + 8) * ldc + cc + 1] = acc[mt][nt][3];
        }
    }
}

// ---- qkv split + l2norm + plane emission + kv output -----------------------
__global__ void qkv_split_kernel(const float* __restrict__ qkv,
                                 const float* __restrict__ tptr,
                                 float* __restrict__ kv_out)
{
    int n2 = blockIdx.x, h = blockIdx.y;
    int t = threadIdx.x;
    int sub = t >> 6, d = t & 63;
    int n = n2 * 2 + sub;
    const float* base = qkv + (long long)n * 3072 + h * 192 + d * 3;
    float q = base[0], k = base[1], v = base[2];

    float sq = q * q, sk = k * k;
#pragma unroll
    for (int o = 16; o; o >>= 1) {
        sq += __shfl_down_sync(0xffffffffu, sq, o);
        sk += __shfl_down_sync(0xffffffffu, sk, o);
    }
    __shared__ float sh[4][2];
    __shared__ float vsh[64];
    int w = t >> 5;
    if ((t & 31) == 0) { sh[w][0] = sq; sh[w][1] = sk; }
    if (sub == 1) vsh[d] = v;
    __syncthreads();
    int wb = sub * 2;
    float nq = sqrtf(sh[wb][0] + sh[wb + 1][0]);
    float nk = sqrtf(sh[wb][1] + sh[wb + 1][1]);
    float temp = tptr[0];
    float qv = q / fmaxf(nq, 1e-12f) * temp;
    float kv = k / fmaxf(nk, 1e-12f);

    int idx = (h * NTOK + n) * HDIM + d;
    kv_out[idx] = k;
    kv_out[NHEAD * NTOK * HDIM + idx] = v;

    float qnb = __shfl_down_sync(0xffffffffu, qv, 1);
    float knb = __shfl_down_sync(0xffffffffu, kv, 1);
    if ((d & 1) == 0) {
        int pi = (h * NTOK + n) * 32 + (d >> 1);
        uint2 pq = pack2_f16(qv, qnb);
        uint2 pk = pack2_f16(kv, knb);
        ((uint32_t*)g_qnh)[pi] = pq.x; ((uint32_t*)g_qnl)[pi] = pq.y;
        ((uint32_t*)g_knh)[pi] = pk.x;
    }
    if (sub == 0) {
        int pi = (h * HDIM + d) * 1024 + n2;
        uint2 pv = pack2_f16(v, vsh[d]);
        ((uint32_t*)g_vth)[pi] = pv.x;
    }
}

// ---------- talking-heads pre mix + pos_bias (R9 measured form) -------------
__global__ void __launch_bounds__(256, 3)
mix_pre_kernel(const float* __restrict__ S0,
               const float* __restrict__ Wpre,
               const float* __restrict__ bpre,
               const float* __restrict__ pb,
               float* __restrict__ s)
{
    int j0 = blockIdx.x * 64, i0 = blockIdx.y * 64;
    if (j0 > i0 + 63) return;
    __shared__ float w[16][16];
    __shared__ float bp[16];
    int t = threadIdx.x;
    w[t >> 4][t & 15] = Wpre[t];
    if (t < 16) bp[t] = bpre[t];
    __syncthreads();

    int tj = t & 63, ti = t >> 6;
    for (int r = 0; r < 16; r++) {
        int i = i0 + (r << 2) + ti;
        int j = j0 + tj;
        if (j > i) continue;
        long long cell = (long long)i * NTOK + j;
        float acc[16];
#pragma unroll
        for (int g = 0; g < 16; g++) acc[g] = bp[g];
#pragma unroll
        for (int h = 0; h < 16; h++) {
            float v = __ldg(S0 + (long long)h * NN + cell);
#pragma unroll
            for (int g = 0; g < 16; g++) acc[g] = fmaf(w[g][h], v, acc[g]);
        }
#pragma unroll
        for (int g = 0; g < 16; g++)
            s[(long long)g * NN + cell] = acc[g] + __ldg(pb + (long long)g * NN + cell);
    }
}

// ---------- per-row softmax stats (causal), single pass ---------------------
__global__ void rowstats_kernel(const float* __restrict__ s,
                                float* __restrict__ m_out, float* __restrict__ invl_out)
{
    int i = blockIdx.x, g = blockIdx.y;
    int len = i + 1;
    const float* row = s + (long long)g * NN + (long long)i * NTOK;
    int t = threadIdx.x;

    float x[8];
#pragma unroll
    for (int b = 0; b < 2; b++) {
        int j0 = t * 4 + b * 1024;
        if (j0 + 3 < len) {
            float4 v = *(const float4*)(row + j0);
            x[b*4+0] = v.x; x[b*4+1] = v.y; x[b*4+2] = v.z; x[b*4+3] = v.w;
        } else {
#pragma unroll
            for (int u = 0; u < 4; u++) {
                int j = j0 + u;
                x[b*4+u] = (j < len) ? row[j] : -3.4e38f;
            }
        }
    }
    float m = -3.4e38f;
#pragma unroll
    for (int u = 0; u < 8; u++) m = fmaxf(m, x[u]);
    float ssum = 0.0f;
#pragma unroll
    for (int u = 0; u < 8; u++) ssum += fexp(x[u] - m);

    __shared__ float rm[256], rs[256];
    rm[t] = m; rs[t] = ssum;
    __syncthreads();
    for (int o = 128; o; o >>= 1) {
        if (t < o) {
            float m1 = rm[t], m2 = rm[t + o];
            float M = fmaxf(m1, m2);
            rs[t] = rs[t] * fexp(m1 - M) + rs[t + o] * fexp(m2 - M);
            rm[t] = M;
        }
        __syncthreads();
    }
    if (t == 0) {
        m_out[g * NTOK + i] = rm[0];
        invl_out[g * NTOK + i] = 1.0f / rs[0];
    }
}

// ---- softmax + post-mix, emits Pm hi/lo fp16 planes ------------------------
__global__ void __launch_bounds__(256, 3)
softmax_mix_kernel(const float* __restrict__ s,
                   const float* __restrict__ m_arr,
                   const float* __restrict__ invl_arr,
                   const float* __restrict__ Wpost,
                   const float* __restrict__ bpost,
                   uint32_t* __restrict__ PmH, uint32_t* __restrict__ PmL)
{
    int j0 = blockIdx.x * 64, i0 = blockIdx.y * 64;
    if (j0 > i0 + 127) return;
    __shared__ float w[16][16];
    __shared__ float bp[16];
    __shared__ float sm[16][64];
    __shared__ float sil[16][64];
    int t = threadIdx.x;
    w[t >> 4][t & 15] = Wpost[t];
    if (t < 16) bp[t] = bpost[t];
#pragma unroll
    for (int e = 0; e < 4; e++) {
        int id = t + e * 256;
        int h = id >> 6, ir = id & 63;
        sm[h][ir]  = m_arr[h * NTOK + i0 + ir];
        sil[h][ir] = invl_arr[h * NTOK + i0 + ir];
    }
    __syncthreads();

    int tj2 = t & 31;
    int ti  = t >> 5;
    int j = j0 + tj2 * 2;
#pragma unroll
    for (int r = 0; r < 8; r++) {
        int ir = r * 8 + ti;
        int i = i0 + ir;
        bool v0 = (j <= i), v1 = (j + 1 <= i);
        float a0[16], a1[16];
#pragma unroll
        for (int g = 0; g < 16; g++) {
            a0[g] = v0 ? bp[g] : 0.0f;
            a1[g] = v1 ? bp[g] : 0.0f;
        }
        if (v0) {
            long long cell = (long long)i * NTOK + j;
#pragma unroll
            for (int h = 0; h < 16; h++) {
                float2 sv = *(const float2*)(s + (long long)h * NN + cell);
                float il = sil[h][ir], mm = sm[h][ir];
                float e0 = fexp(sv.x - mm) * il;
                float e1 = v1 ? fexp(sv.y - mm) * il : 0.0f;
#pragma unroll
                for (int g = 0; g < 16; g++) {
                    a0[g] = fmaf(w[g][h], e0, a0[g]);
                    a1[g] = fmaf(w[g][h], e1, a1[g]);
                }
            }
        }
        long long pidx = (long long)i * 1024 + tj2 + (j0 >> 1);
#pragma unroll
        for (int g = 0; g < 16; g++) {
            uint2 pk = pack2_f16(a0[g], a1[g]);
            PmH[(long long)g * (NN / 2) + pidx] = pk.x;
            PmL[(long long)g * (NN / 2) + pidx] = pk.y;
        }
    }
}

// ---------------------------------------------------------------------------
extern "C" void kernel_launch(void* const* d_in, const int* in_sizes, int n_in,
                              void* d_out, int out_size)
{
    const float* x     = (const float*)d_in[0];
    const float* pb    = (const float*)d_in[1];
    const float* Wqkv  = (const float*)d_in[3];
    const float* Wout  = (const float*)d_in[4];
    const float* temp  = (const float*)d_in[5];
    const float* Wpre  = (const float*)d_in[6];
    const float* bpre  = (const float*)d_in[7];
    const float* Wpost = (const float*)d_in[8];
    const float* bpost = (const float*)d_in[9];
    float* out = (float*)d_out;
    float* kv_out = out + NTOK * CDIM;

    float *qkv_p, *bufA_p, *bufB_p, *m_p, *invl_p, *o2pp, *outp;
    cudaGetSymbolAddress((void**)&qkv_p, g_qkv);
    cudaGetSymbolAddress((void**)&bufA_p, g_bufA);
    cudaGetSymbolAddress((void**)&bufB_p, g_bufB);
    cudaGetSymbolAddress((void**)&m_p, g_m);
    cudaGetSymbolAddress((void**)&invl_p, g_invl);
    cudaGetSymbolAddress((void**)&o2pp, g_o2p);
    cudaGetSymbolAddress((void**)&outp, g_outp);

    __half *xh, *xl, *wqh, *wql, *woh, *wol, *qnh, *qnl, *knh, *vth, *o2h, *o2l;
    cudaGetSymbolAddress((void**)&xh, g_xh);
    cudaGetSymbolAddress((void**)&xl, g_xl);
    cudaGetSymbolAddress((void**)&wqh, g_wqh);
    cudaGetSymbolAddress((void**)&wql, g_wql);
    cudaGetSymbolAddress((void**)&woh, g_woh);
    cudaGetSymbolAddress((void**)&wol, g_wol);
    cudaGetSymbolAddress((void**)&qnh, g_qnh);
    cudaGetSymbolAddress((void**)&qnl, g_qnl);
    cudaGetSymbolAddress((void**)&knh, g_knh);
    cudaGetSymbolAddress((void**)&vth, g_vth);
    cudaGetSymbolAddress((void**)&o2h, g_o2h);
    cudaGetSymbolAddress((void**)&o2l, g_o2l);

    cudaFuncSetAttribute(gemm_lm, cudaFuncAttributeMaxDynamicSharedMemorySize,
                         (int)GEMM_SMEM);
    cudaFuncSetAttribute(gemm_lm128, cudaFuncAttributeMaxDynamicSharedMemorySize,
                         (int)GEMM128_SMEM);

    const long long PSZ = 2048LL * 1024;

    // 0) pack fp32 inputs into hi/lo fp16 planes
    pack_planes<<<2048, 256>>>(x, xh, xl, 2048 * 1024);
    pack_planes<<<3072, 256>>>(Wqkv, wqh, wql, 3072 * 1024);
    pack_planes<<<1024, 256>>>(Wout, woh, wol, 1024 * 1024);

    // 1) qkv = x @ Wqkv^T : [2048,3072]  (128x128 tiles, 2-MMA)
    gemm_lm128<<<dim3(24, 16), 256, GEMM128_SMEM>>>(
        xh, xl, wqh, qkv_p, 1024, 1024, 1024, 3072);

    // 2) split + l2norm + qn(h+l)/kn(h)/vT(h) planes + kv output
    qkv_split_kernel<<<dim3(1024, NHEAD), 128>>>(qkv_p, temp, kv_out);

    // 3) S0[h] = qn[h] @ kn[h]^T (causal tiles only) -> bufA fp32
    gemm_lm<<<dim3(32, 16, NHEAD), 256, GEMM_SMEM>>>(
        qnh, qnl, knh, bufA_p, 64, 64, 64, 2048,
        (long long)NTOK * HDIM, (long long)NTOK * HDIM, (long long)NN, 0, 1);

    // 4) pre talking-heads mix + pos_bias -> s
    mix_pre_kernel<<<dim3(32, 32), 256>>>(bufA_p, Wpre, bpre, pb, bufB_p);

    // 5) per-row max / inv-sum-exp
    rowstats_kernel<<<dim3(NTOK, NHEAD), 256>>>(bufB_p, m_p, invl_p);

    // 6) softmax + post-mix -> Pm hi/lo fp16 planes (reuses bufA bytes)
    uint32_t* PmH = (uint32_t*)bufA_p;
    uint32_t* PmL = PmH + (long long)NHEAD * NN / 2;
    softmax_mix_kernel<<<dim3(32, 32), 256>>>(
        bufB_p, m_p, invl_p, Wpost, bpost, PmH, PmL);

    // 7) PV split-K x4: o2part[part] = Pm @ v
    const __half* PmHb = (const __half*)PmH;
    const __half* PmLb = (const __half*)PmL;
    gemm_lm<<<dim3(1, 16, NHEAD * 4), 256, GEMM_SMEM>>>(
        PmHb, PmLb, vth, o2pp, 2048, 2048, 2048, 1024,
        (long long)NN, (long long)HDIM * NTOK, 64, PSZ, 2);

    // 8) combine partials -> o2 planes
    combine_pack4<<<2048, 256>>>(o2pp, o2pp + PSZ, o2pp + 2 * PSZ, o2pp + 3 * PSZ,
                                 o2h, o2l, 2048 * 1024);

    // 9) out = o2 @ Wout^T (split-K x4, fp32 partials)
    gemm_lm<<<dim3(16, 16, 4), 256, GEMM_SMEM>>>(
        o2h, o2l, woh, outp, 1024, 1024, 1024, 1024,
        0, 0, 0, PSZ, 3);

    // 10) combine out partials
    combine_out4<<<2048, 256>>>(outp, outp + PSZ, outp + 2 * PSZ, outp + 3 * PSZ,
                                out, 2048 * 1024);
}

// round 16
// speedup vs baseline: 1.1951x; 1.0636x over previous
#include <cuda_runtime.h>
#include <cuda_bf16.h>
#include <cuda_fp16.h>
#include <cstdint>

// ---------------------------------------------------------------------------
// transformer_75419625718098: talking-heads causal attention
// B=1, N=2048, C=1024, H=16, D=64
// Round 16: Pm stored hi-only (PV becomes 1-MMA, softmax_mix stores halved);
// dead lo-plane packs removed. gemm_lm gains nterms flag.
// ---------------------------------------------------------------------------

#define NTOK 2048
#define NHEAD 16
#define HDIM 64
#define CDIM 1024
#define NN (2048*2048)

// 64-wide gemm: stage = Ahi 4K + Alo 4K + Bhi 2K
#define STG_BYTES 10240
#define GEMM_SMEM (4 * STG_BYTES)          // 40960
// 128-wide gemm (qkv): stage = Ahi 4K + Alo 4K + Bhi 4K
#define STG128 12288
#define GEMM128_SMEM (4 * STG128)          // 49152

// ------------------------- device scratch ----------------------------------
__device__ float g_qkv[2048 * 3072];
__device__ float g_bufA[(long long)NHEAD * NN]; // S0 fp32 -> Pm hi plane
__device__ float g_bufB[(long long)NHEAD * NN]; // s (mixed logits)
__device__ float g_m   [NHEAD * NTOK];
__device__ float g_invl[NHEAD * NTOK];
__device__ float g_o2p [4LL * 2048 * 1024];     // PV split-K partials (x4)
__device__ float g_outp[4LL * 2048 * 1024];     // out-proj split-K partials (x4)
// fp16 planes
__device__ __half g_xh [2048 * 1024], g_xl [2048 * 1024];
__device__ __half g_wqh[3072 * 1024];
__device__ __half g_woh[1024 * 1024];
__device__ __half g_qnh[NHEAD * NTOK * HDIM], g_qnl[NHEAD * NTOK * HDIM];
__device__ __half g_knh[NHEAD * NTOK * HDIM];
__device__ __half g_vth[NHEAD * HDIM * NTOK];
__device__ __half g_o2h[2048 * 1024], g_o2l[2048 * 1024];

// fast exp on the FMA pipe
__device__ __forceinline__ float fexp(float x) {
    float t = fmaxf(x * 1.4426950408889634f, -126.0f);
    int ei = __float2int_rd(t);
    float f = t - (float)ei;
    float y = 0.69314718055994531f * f;
    float p = fmaf(y, 1.3888889e-3f, 8.3333333e-3f);
    p = fmaf(y, p, 4.1666667e-2f);
    p = fmaf(y, p, 1.6666667e-1f);
    p = fmaf(y, p, 0.5f);
    p = fmaf(y, p, 1.0f);
    p = fmaf(y, p, 1.0f);
    return p * __int_as_float((ei + 127) << 23);
}

// (x0,x1) -> (hi_f16x2, lo_f16x2)
__device__ __forceinline__ uint2 pack2_f16(float x0, float x1) {
    __half2 h2 = __floats2half2_rn(x0, x1);
    float2 hf = __half22float2(h2);
    __half2 l2 = __floats2half2_rn(x0 - hf.x, x1 - hf.y);
    uint2 r;
    r.x = *reinterpret_cast<uint32_t*>(&h2);
    r.y = *reinterpret_cast<uint32_t*>(&l2);
    return r;
}
__device__ __forceinline__ uint32_t pack2_f16_hi(float x0, float x1) {
    __half2 h2 = __floats2half2_rn(x0, x1);
    return *reinterpret_cast<uint32_t*>(&h2);
}

__device__ __forceinline__ void mma_f16(float* c, const uint32_t* a, const uint32_t* b) {
    asm volatile(
        "mma.sync.aligned.m16n8k16.row.col.f32.f16.f16.f32 "
        "{%0,%1,%2,%3},{%4,%5,%6,%7},{%8,%9},{%0,%1,%2,%3};"
        : "+f"(c[0]), "+f"(c[1]), "+f"(c[2]), "+f"(c[3])
        : "r"(a[0]), "r"(a[1]), "r"(a[2]), "r"(a[3]), "r"(b[0]), "r"(b[1]));
}

__device__ __forceinline__ void ldsm4(uint32_t* r, uint32_t addr) {
    asm volatile("ldmatrix.sync.aligned.m8n8.x4.shared.b16 {%0,%1,%2,%3}, [%4];"
                 : "=r"(r[0]), "=r"(r[1]), "=r"(r[2]), "=r"(r[3]) : "r"(addr));
}

// ---------------- pack fp32 -> hi/lo fp16 planes ----------------------------
__global__ void pack_planes(const float* __restrict__ s,
                            __half* __restrict__ hi,
                            __half* __restrict__ lo, int n)
{
    int i = (blockIdx.x * 256 + threadIdx.x) * 4;
    if (i >= n) return;
    float4 v = *(const float4*)(s + i);
    uint2 p01 = pack2_f16(v.x, v.y);
    uint2 p23 = pack2_f16(v.z, v.w);
    *(uint2*)(hi + i) = make_uint2(p01.x, p23.x);
    *(uint2*)(lo + i) = make_uint2(p01.y, p23.y);
}

// ---------------- pack fp32 -> hi fp16 plane only ---------------------------
__global__ void pack_hi(const float* __restrict__ s, __half* __restrict__ hi, int n)
{
    int i = (blockIdx.x * 256 + threadIdx.x) * 4;
    if (i >= n) return;
    float4 v = *(const float4*)(s + i);
    *(uint2*)(hi + i) = make_uint2(pack2_f16_hi(v.x, v.y), pack2_f16_hi(v.z, v.w));
}

// ------------- combine 4 split-K partials + pack to planes ------------------
__global__ void combine_pack4(const float* __restrict__ p0, const float* __restrict__ p1,
                              const float* __restrict__ p2, const float* __restrict__ p3,
                              __half* __restrict__ hi, __half* __restrict__ lo, int n)
{
    int i = (blockIdx.x * 256 + threadIdx.x) * 4;
    if (i >= n) return;
    float4 a = *(const float4*)(p0 + i);
    float4 b = *(const float4*)(p1 + i);
    float4 c = *(const float4*)(p2 + i);
    float4 d = *(const float4*)(p3 + i);
    uint2 p01 = pack2_f16(a.x + b.x + c.x + d.x, a.y + b.y + c.y + d.y);
    uint2 p23 = pack2_f16(a.z + b.z + c.z + d.z, a.w + b.w + c.w + d.w);
    *(uint2*)(hi + i) = make_uint2(p01.x, p23.x);
    *(uint2*)(lo + i) = make_uint2(p01.y, p23.y);
}

// ------------- combine 4 split-K partials (fp32 out) ------------------------
__global__ void combine_out4(const float* __restrict__ p0, const float* __restrict__ p1,
                             const float* __restrict__ p2, const float* __restrict__ p3,
                             float* __restrict__ o, int n)
{
    int i = (blockIdx.x * 256 + threadIdx.x) * 4;
    if (i >= n) return;
    float4 a = *(const float4*)(p0 + i);
    float4 b = *(const float4*)(p1 + i);
    float4 c = *(const float4*)(p2 + i);
    float4 d = *(const float4*)(p3 + i);
    *(float4*)(o + i) = make_float4(a.x + b.x + c.x + d.x, a.y + b.y + c.y + d.y,
                                    a.z + b.z + c.z + d.z, a.w + b.w + c.w + d.w);
}

// ---------- split-fp16 GEMM (128x64): C = A*B^T -----------------------------
// nterms=2: hh + lh (A hi+lo). nterms=1: hh only (Al unused).
// mode 0: plain batched. mode 1: causal skip (QK).
// mode 2: causal split-K x4 PV (z = 4*g+part). mode 3: plain split-K x4.
__global__ void __launch_bounds__(256, 3)
gemm_lm(const __half* __restrict__ Ah, const __half* __restrict__ Al,
        const __half* __restrict__ Bh,
        float* __restrict__ C,
        int K, int lda, int ldb, int ldc,
        long long sA, long long sB, long long sC, long long ssplit,
        int mode, int nterms)
{
    int j0 = blockIdx.x * 64;
    int i0 = blockIdx.y * 128;
    if (mode == 1 && j0 > i0 + 127) return;
    int bz = blockIdx.z;
    int g, part;
    if (mode == 2)      { g = bz >> 2; part = bz & 3; }
    else if (mode == 3) { g = 0;       part = bz;     }
    else                { g = bz;      part = 0;      }
    Ah += (long long)g * sA; Al += (long long)g * sA;
    Bh += (long long)g * sB;
    C  += (long long)g * sC + (long long)part * ssplit;

    int ks = 0, ke = K;
    if (mode == 2) {
        int Keff = min(K, i0 + 128);
        int q1 = (Keff >> 2) & ~15;
        int q2 = (Keff >> 1) & ~15;
        int q3 = ((3 * Keff) >> 2) & ~15;
        ks = (part == 0) ? 0  : (part == 1) ? q1 : (part == 2) ? q2 : q3;
        ke = (part == 0) ? q1 : (part == 1) ? q2 : (part == 2) ? q3 : Keff;
    } else if (mode == 3) {
        int quarter = K >> 2;
        ks = part * quarter;
        ke = ks + quarter;
    }
    int KC = (ke - ks) >> 4;
    bool two = (nterms == 2);

    extern __shared__ char smem[];
    uint32_t sb0 = (uint32_t)__cvta_generic_to_shared(smem);

    int t = threadIdx.x;
    int lane = t & 31;
    int wid  = t >> 5;
    int wm   = (wid & 3) * 32;
    int wn   = (wid >> 2) * 32;

    int arow = t >> 1, ahf = t & 1;
    const __half* gA0 = Ah + (long long)(i0 + arow) * lda + ahf * 8;
    const __half* gA1 = Al + (long long)(i0 + arow) * lda + ahf * 8;
    uint32_t aoff = (uint32_t)((t ^ ((t >> 3) & 1)) * 16);
    bool hasB = (t < 128);
    int brow = t >> 1, bhf = t & 1;
    const __half* gB = Bh + (long long)(j0 + brow) * ldb + bhf * 8;
    uint32_t boff = 8192 + (uint32_t)((t ^ ((t >> 3) & 1)) * 16);

#define ISSUE(cc)                                                             \
    do {                                                                      \
        uint32_t base_ = sb0 + (uint32_t)(((cc) & 3) * STG_BYTES);            \
        int k_ = ks + (cc) * 16;                                              \
        asm volatile("cp.async.ca.shared.global [%0], [%1], 16;"              \
                     :: "r"(base_ + aoff), "l"(gA0 + k_) : "memory");         \
        if (two)                                                              \
            asm volatile("cp.async.ca.shared.global [%0], [%1], 16;"          \
                         :: "r"(base_ + 4096 + aoff), "l"(gA1 + k_) : "memory"); \
        if (hasB)                                                             \
            asm volatile("cp.async.ca.shared.global [%0], [%1], 16;"          \
                         :: "r"(base_ + boff), "l"(gB + k_) : "memory");      \
    } while (0)

    uint32_t addrA[2][2], addrB[2];
#pragma unroll
    for (int mt = 0; mt < 2; mt++) {
        int row = wm + mt * 16 + (lane & 15);
        int hf = lane >> 4;
        int ca = row * 2 + hf;
        uint32_t ph = (uint32_t)((ca ^ ((ca >> 3) & 1)) * 16);
        addrA[mt][0] = sb0 + ph;
        addrA[mt][1] = sb0 + 4096 + ph;
    }
#pragma unroll
    for (int ng = 0; ng < 2; ng++) {
        int n = wn + ng * 16 + ((lane >> 4) & 1) * 8 + (lane & 7);
        int hf = (lane >> 3) & 1;
        int cb = n * 2 + hf;
        uint32_t ph = (uint32_t)((cb ^ ((cb >> 3) & 1)) * 16);
        addrB[ng] = sb0 + 8192 + ph;
    }

#pragma unroll
    for (int s = 0; s < 3; s++) {
        if (s < KC) ISSUE(s);
        asm volatile("cp.async.commit_group;" ::: "memory");
    }

    float acc[2][4][4];
#pragma unroll
    for (int mt = 0; mt < 2; mt++)
#pragma unroll
        for (int nt = 0; nt < 4; nt++)
#pragma unroll
            for (int e = 0; e < 4; e++) acc[mt][nt][e] = 0.0f;

    for (int c = 0; c < KC; c++) {
        asm volatile("cp.async.wait_group 2;" ::: "memory");
        __syncthreads();
        {
            int s = c + 3;
            if (s < KC) ISSUE(s);
            asm volatile("cp.async.commit_group;" ::: "memory");
        }
        uint32_t st = (uint32_t)((c & 3) * STG_BYTES);

        uint32_t ah[2][4], bb[2][4];
        ldsm4(ah[0], addrA[0][0] + st);
        ldsm4(ah[1], addrA[1][0] + st);
        ldsm4(bb[0], addrB[0] + st);
        ldsm4(bb[1], addrB[1] + st);
#pragma unroll
        for (int mt = 0; mt < 2; mt++)
#pragma unroll
            for (int nt = 0; nt < 4; nt++)
                mma_f16(acc[mt][nt], ah[mt], &bb[nt >> 1][(nt & 1) * 2]);
        if (two) {
            uint32_t al[2][4];
            ldsm4(al[0], addrA[0][1] + st);
            ldsm4(al[1], addrA[1][1] + st);
#pragma unroll
            for (int mt = 0; mt < 2; mt++)
#pragma unroll
                for (int nt = 0; nt < 4; nt++)
                    mma_f16(acc[mt][nt], al[mt], &bb[nt >> 1][(nt & 1) * 2]);
        }
    }
#undef ISSUE

    int gid = lane >> 2, tig = lane & 3;
#pragma unroll
    for (int mt = 0; mt < 2; mt++) {
        int r = i0 + wm + mt * 16 + gid;
#pragma unroll
        for (int nt = 0; nt < 4; nt++) {
            int cc = j0 + wn + nt * 8 + tig * 2;
            C[(long long)r * ldc + cc]           = acc[mt][nt][0];
            C[(long long)r * ldc + cc + 1]       = acc[mt][nt][1];
            C[(long long)(r + 8) * ldc + cc]     = acc[mt][nt][2];
            C[(long long)(r + 8) * ldc + cc + 1] = acc[mt][nt][3];
        }
    }
}

// ---------- split-fp16 2-MMA GEMM (128x128): C = A*B^T (qkv) ----------------
__global__ void __launch_bounds__(256, 2)
gemm_lm128(const __half* __restrict__ Ah, const __half* __restrict__ Al,
           const __half* __restrict__ Bh,
           float* __restrict__ C, int K, int lda, int ldb, int ldc)
{
    int j0 = blockIdx.x * 128;
    int i0 = blockIdx.y * 128;
    int KC = K >> 4;

    extern __shared__ char smem[];
    uint32_t sb0 = (uint32_t)__cvta_generic_to_shared(smem);

    int t = threadIdx.x;
    int lane = t & 31;
    int wid  = t >> 5;
    int wm   = (wid & 1) * 64;
    int wn   = (wid >> 1) * 32;

    int arow = t >> 1, ahf = t & 1;
    const __half* gA0 = Ah + (long long)(i0 + arow) * lda + ahf * 8;
    const __half* gA1 = Al + (long long)(i0 + arow) * lda + ahf * 8;
    const __half* gB  = Bh + (long long)(j0 + arow) * ldb + ahf * 8;
    uint32_t coff = (uint32_t)((t ^ ((t >> 3) & 1)) * 16);

#define ISSUE8(cc)                                                            \
    do {                                                                      \
        uint32_t base_ = sb0 + (uint32_t)(((cc) & 3) * STG128);               \
        int k_ = (cc) * 16;                                                   \
        asm volatile("cp.async.ca.shared.global [%0], [%1], 16;"              \
                     :: "r"(base_ + coff), "l"(gA0 + k_) : "memory");         \
        asm volatile("cp.async.ca.shared.global [%0], [%1], 16;"              \
                     :: "r"(base_ + 4096 + coff), "l"(gA1 + k_) : "memory");  \
        asm volatile("cp.async.ca.shared.global [%0], [%1], 16;"              \
                     :: "r"(base_ + 8192 + coff), "l"(gB + k_) : "memory");   \
    } while (0)

    uint32_t addrA[4][2], addrB[2];
#pragma unroll
    for (int mt = 0; mt < 4; mt++) {
        int row = wm + mt * 16 + (lane & 15);
        int hf = lane >> 4;
        int ca = row * 2 + hf;
        uint32_t ph = (uint32_t)((ca ^ ((ca >> 3) & 1)) * 16);
        addrA[mt][0] = sb0 + ph;
        addrA[mt][1] = sb0 + 4096 + ph;
    }
#pragma unroll
    for (int ng = 0; ng < 2; ng++) {
        int n = wn + ng * 16 + ((lane >> 4) & 1) * 8 + (lane & 7);
        int hf = (lane >> 3) & 1;
        int cb = n * 2 + hf;
        uint32_t ph = (uint32_t)((cb ^ ((cb >> 3) & 1)) * 16);
        addrB[ng] = sb0 + 8192 + ph;
    }

#pragma unroll
    for (int s = 0; s < 3; s++) {
        if (s < KC) ISSUE8(s);
        asm volatile("cp.async.commit_group;" ::: "memory");
    }

    float acc[4][4][4];
#pragma unroll
    for (int mt = 0; mt < 4; mt++)
#pragma unroll
        for (int nt = 0; nt < 4; nt++)
#pragma unroll
            for (int e = 0; e < 4; e++) acc[mt][nt][e] = 0.0f;

    for (int c = 0; c < KC; c++) {
        asm volatile("cp.async.wait_group 2;" ::: "memory");
        __syncthreads();
        {
            int s = c + 3;
            if (s < KC) ISSUE8(s);
            asm volatile("cp.async.commit_group;" ::: "memory");
        }
        uint32_t st = (uint32_t)((c & 3) * STG128);

        uint32_t ah[4][4], bb[2][4];
        ldsm4(ah[0], addrA[0][0] + st);
        ldsm4(ah[1], addrA[1][0] + st);
        ldsm4(ah[2], addrA[2][0] + st);
        ldsm4(ah[3], addrA[3][0] + st);
        ldsm4(bb[0], addrB[0] + st);
        ldsm4(bb[1], addrB[1] + st);
        // hh
#pragma unroll
        for (int mt = 0; mt < 4; mt++)
#pragma unroll
            for (int nt = 0; nt < 4; nt++)
                mma_f16(acc[mt][nt], ah[mt], &bb[nt >> 1][(nt & 1) * 2]);
        // lh
        {
            uint32_t al[4][4];
            ldsm4(al[0], addrA[0][1] + st);
            ldsm4(al[1], addrA[1][1] + st);
            ldsm4(al[2], addrA[2][1] + st);
            ldsm4(al[3], addrA[3][1] + st);
#pragma unroll
            for (int mt = 0; mt < 4; mt++)
#pragma unroll
                for (int nt = 0; nt < 4; nt++)
                    mma_f16(acc[mt][nt], al[mt], &bb[nt >> 1][(nt & 1) * 2]);
        }
    }
#undef ISSUE8

    int gid = lane >> 2, tig = lane & 3;
#pragma unroll
    for (int mt = 0; mt < 4; mt++) {
        int r = i0 + wm + mt * 16 + gid;
#pragma unroll
        for (int nt = 0; nt < 4; nt++) {
            int cc = j0 + wn + nt * 8 + tig * 2;
            C[(long long)r * ldc + cc]           = acc[mt][nt][0];
            C[(long long)r * ldc + cc + 1]       = acc[mt][nt][1];
            C[(long long)(r + 8) * ldc + cc]     = acc[mt][nt][2];
            C[(long long)(r + 8) * ldc + cc + 1] = acc[mt][nt][3];
        }
    }
}

// ---- qkv split + l2norm + plane emission + kv output -----------------------
__global__ void qkv_split_kernel(const float* __restrict__ qkv,
                                 const float* __restrict__ tptr,
                                 float* __restrict__ kv_out)
{
    int n2 = blockIdx.x, h = blockIdx.y;
    int t = threadIdx.x;
    int sub = t >> 6, d = t & 63;
    int n = n2 * 2 + sub;
    const float* base = qkv + (long long)n * 3072 + h * 192 + d * 3;
    float q = base[0], k = base[1], v = base[2];

    float sq = q * q, sk = k * k;
#pragma unroll
    for (int o = 16; o; o >>= 1) {
        sq += __shfl_down_sync(0xffffffffu, sq, o);
        sk += __shfl_down_sync(0xffffffffu, sk, o);
    }
    __shared__ float sh[4][2];
    __shared__ float vsh[64];
    int w = t >> 5;
    if ((t & 31) == 0) { sh[w][0] = sq; sh[w][1] = sk; }
    if (sub == 1) vsh[d] = v;
    __syncthreads();
    int wb = sub * 2;
    float nq = sqrtf(sh[wb][0] + sh[wb + 1][0]);
    float nk = sqrtf(sh[wb][1] + sh[wb + 1][1]);
    float temp = tptr[0];
    float qv = q / fmaxf(nq, 1e-12f) * temp;
    float kv = k / fmaxf(nk, 1e-12f);

    int idx = (h * NTOK + n) * HDIM + d;
    kv_out[idx] = k;
    kv_out[NHEAD * NTOK * HDIM + idx] = v;

    float qnb = __shfl_down_sync(0xffffffffu, qv, 1);
    float knb = __shfl_down_sync(0xffffffffu, kv, 1);
    if ((d & 1) == 0) {
        int pi = (h * NTOK + n) * 32 + (d >> 1);
        uint2 pq = pack2_f16(qv, qnb);
        ((uint32_t*)g_qnh)[pi] = pq.x; ((uint32_t*)g_qnl)[pi] = pq.y;
        ((uint32_t*)g_knh)[pi] = pack2_f16_hi(kv, knb);
    }
    if (sub == 0) {
        int pi = (h * HDIM + d) * 1024 + n2;
        ((uint32_t*)g_vth)[pi] = pack2_f16_hi(v, vsh[d]);
    }
}

// ---------- talking-heads pre mix + pos_bias (R9 measured form) -------------
__global__ void __launch_bounds__(256, 3)
mix_pre_kernel(const float* __restrict__ S0,
               const float* __restrict__ Wpre,
               const float* __restrict__ bpre,
               const float* __restrict__ pb,
               float* __restrict__ s)
{
    int j0 = blockIdx.x * 64, i0 = blockIdx.y * 64;
    if (j0 > i0 + 63) return;
    __shared__ float w[16][16];
    __shared__ float bp[16];
    int t = threadIdx.x;
    w[t >> 4][t & 15] = Wpre[t];
    if (t < 16) bp[t] = bpre[t];
    __syncthreads();

    int tj = t & 63, ti = t >> 6;
    for (int r = 0; r < 16; r++) {
        int i = i0 + (r << 2) + ti;
        int j = j0 + tj;
        if (j > i) continue;
        long long cell = (long long)i * NTOK + j;
        float acc[16];
#pragma unroll
        for (int g = 0; g < 16; g++) acc[g] = bp[g];
#pragma unroll
        for (int h = 0; h < 16; h++) {
            float v = __ldg(S0 + (long long)h * NN + cell);
#pragma unroll
            for (int g = 0; g < 16; g++) acc[g] = fmaf(w[g][h], v, acc[g]);
        }
#pragma unroll
        for (int g = 0; g < 16; g++)
            s[(long long)g * NN + cell] = acc[g] + __ldg(pb + (long long)g * NN + cell);
    }
}

// ---------- per-row softmax stats (causal), single pass ---------------------
__global__ void rowstats_kernel(const float* __restrict__ s,
                                float* __restrict__ m_out, float* __restrict__ invl_out)
{
    int i = blockIdx.x, g = blockIdx.y;
    int len = i + 1;
    const float* row = s + (long long)g * NN + (long long)i * NTOK;
    int t = threadIdx.x;

    float x[8];
#pragma unroll
    for (int b = 0; b < 2; b++) {
        int j0 = t * 4 + b * 1024;
        if (j0 + 3 < len) {
            float4 v = *(const float4*)(row + j0);
            x[b*4+0] = v.x; x[b*4+1] = v.y; x[b*4+2] = v.z; x[b*4+3] = v.w;
        } else {
#pragma unroll
            for (int u = 0; u < 4; u++) {
                int j = j0 + u;
                x[b*4+u] = (j < len) ? row[j] : -3.4e38f;
            }
        }
    }
    float m = -3.4e38f;
#pragma unroll
    for (int u = 0; u < 8; u++) m = fmaxf(m, x[u]);
    float ssum = 0.0f;
#pragma unroll
    for (int u = 0; u < 8; u++) ssum += fexp(x[u] - m);

    __shared__ float rm[256], rs[256];
    rm[t] = m; rs[t] = ssum;
    __syncthreads();
    for (int o = 128; o; o >>= 1) {
        if (t < o) {
            float m1 = rm[t], m2 = rm[t + o];
            float M = fmaxf(m1, m2);
            rs[t] = rs[t] * fexp(m1 - M) + rs[t + o] * fexp(m2 - M);
            rm[t] = M;
        }
        __syncthreads();
    }
    if (t == 0) {
        m_out[g * NTOK + i] = rm[0];
        invl_out[g * NTOK + i] = 1.0f / rs[0];
    }
}

// ---- softmax + post-mix, emits Pm hi fp16 plane only -----------------------
__global__ void __launch_bounds__(256, 3)
softmax_mix_kernel(const float* __restrict__ s,
                   const float* __restrict__ m_arr,
                   const float* __restrict__ invl_arr,
                   const float* __restrict__ Wpost,
                   const float* __restrict__ bpost,
                   uint32_t* __restrict__ PmH)
{
    int j0 = blockIdx.x * 64, i0 = blockIdx.y * 64;
    if (j0 > i0 + 127) return;
    __shared__ float w[16][16];
    __shared__ float bp[16];
    __shared__ float sm[16][64];
    __shared__ float sil[16][64];
    int t = threadIdx.x;
    w[t >> 4][t & 15] = Wpost[t];
    if (t < 16) bp[t] = bpost[t];
#pragma unroll
    for (int e = 0; e < 4; e++) {
        int id = t + e * 256;
        int h = id >> 6, ir = id & 63;
        sm[h][ir]  = m_arr[h * NTOK + i0 + ir];
        sil[h][ir] = invl_arr[h * NTOK + i0 + ir];
    }
    __syncthreads();

    int tj2 = t & 31;
    int ti  = t >> 5;
    int j = j0 + tj2 * 2;
#pragma unroll
    for (int r = 0; r < 8; r++) {
        int ir = r * 8 + ti;
        int i = i0 + ir;
        bool v0 = (j <= i), v1 = (j + 1 <= i);
        float a0[16], a1[16];
#pragma unroll
        for (int g = 0; g < 16; g++) {
            a0[g] = v0 ? bp[g] : 0.0f;
            a1[g] = v1 ? bp[g] : 0.0f;
        }
        if (v0) {
            long long cell = (long long)i * NTOK + j;
#pragma unroll
            for (int h = 0; h < 16; h++) {
                float2 sv = *(const float2*)(s + (long long)h * NN + cell);
                float il = sil[h][ir], mm = sm[h][ir];
                float e0 = fexp(sv.x - mm) * il;
                float e1 = v1 ? fexp(sv.y - mm) * il : 0.0f;
#pragma unroll
                for (int g = 0; g < 16; g++) {
                    a0[g] = fmaf(w[g][h], e0, a0[g]);
                    a1[g] = fmaf(w[g][h], e1, a1[g]);
                }
            }
        }
        long long pidx = (long long)i * 1024 + tj2 + (j0 >> 1);
#pragma unroll
        for (int g = 0; g < 16; g++)
            PmH[(long long)g * (NN / 2) + pidx] = pack2_f16_hi(a0[g], a1[g]);
    }
}

// ---------------------------------------------------------------------------
extern "C" void kernel_launch(void* const* d_in, const int* in_sizes, int n_in,
                              void* d_out, int out_size)
{
    const float* x     = (const float*)d_in[0];
    const float* pb    = (const float*)d_in[1];
    const float* Wqkv  = (const float*)d_in[3];
    const float* Wout  = (const float*)d_in[4];
    const float* temp  = (const float*)d_in[5];
    const float* Wpre  = (const float*)d_in[6];
    const float* bpre  = (const float*)d_in[7];
    const float* Wpost = (const float*)d_in[8];
    const float* bpost = (const float*)d_in[9];
    float* out = (float*)d_out;
    float* kv_out = out + NTOK * CDIM;

    float *qkv_p, *bufA_p, *bufB_p, *m_p, *invl_p, *o2pp, *outp;
    cudaGetSymbolAddress((void**)&qkv_p, g_qkv);
    cudaGetSymbolAddress((void**)&bufA_p, g_bufA);
    cudaGetSymbolAddress((void**)&bufB_p, g_bufB);
    cudaGetSymbolAddress((void**)&m_p, g_m);
    cudaGetSymbolAddress((void**)&invl_p, g_invl);
    cudaGetSymbolAddress((void**)&o2pp, g_o2p);
    cudaGetSymbolAddress((void**)&outp, g_outp);

    __half *xh, *xl, *wqh, *woh, *qnh, *qnl, *knh, *vth, *o2h, *o2l;
    cudaGetSymbolAddress((void**)&xh, g_xh);
    cudaGetSymbolAddress((void**)&xl, g_xl);
    cudaGetSymbolAddress((void**)&wqh, g_wqh);
    cudaGetSymbolAddress((void**)&woh, g_woh);
    cudaGetSymbolAddress((void**)&qnh, g_qnh);
    cudaGetSymbolAddress((void**)&qnl, g_qnl);
    cudaGetSymbolAddress((void**)&knh, g_knh);
    cudaGetSymbolAddress((void**)&vth, g_vth);
    cudaGetSymbolAddress((void**)&o2h, g_o2h);
    cudaGetSymbolAddress((void**)&o2l, g_o2l);

    cudaFuncSetAttribute(gemm_lm, cudaFuncAttributeMaxDynamicSharedMemorySize,
                         (int)GEMM_SMEM);
    cudaFuncSetAttribute(gemm_lm128, cudaFuncAttributeMaxDynamicSharedMemorySize,
                         (int)GEMM128_SMEM);

    const long long PSZ = 2048LL * 1024;

    // 0) pack fp32 inputs (A-side: hi+lo; B-side: hi only)
    pack_planes<<<2048, 256>>>(x, xh, xl, 2048 * 1024);
    pack_hi<<<3072, 256>>>(Wqkv, wqh, 3072 * 1024);
    pack_hi<<<1024, 256>>>(Wout, woh, 1024 * 1024);

    // 1) qkv = x @ Wqkv^T : [2048,3072]  (128x128 tiles, 2-MMA)
    gemm_lm128<<<dim3(24, 16), 256, GEMM128_SMEM>>>(
        xh, xl, wqh, qkv_p, 1024, 1024, 1024, 3072);

    // 2) split + l2norm + qn(h+l)/kn(h)/vT(h) planes + kv output
    qkv_split_kernel<<<dim3(1024, NHEAD), 128>>>(qkv_p, temp, kv_out);

    // 3) S0[h] = qn[h] @ kn[h]^T (causal tiles only, 2-term) -> bufA fp32
    gemm_lm<<<dim3(32, 16, NHEAD), 256, GEMM_SMEM>>>(
        qnh, qnl, knh, bufA_p, 64, 64, 64, 2048,
        (long long)NTOK * HDIM, (long long)NTOK * HDIM, (long long)NN, 0, 1, 2);

    // 4) pre talking-heads mix + pos_bias -> s
    mix_pre_kernel<<<dim3(32, 32), 256>>>(bufA_p, Wpre, bpre, pb, bufB_p);

    // 5) per-row max / inv-sum-exp
    rowstats_kernel<<<dim3(NTOK, NHEAD), 256>>>(bufB_p, m_p, invl_p);

    // 6) softmax + post-mix -> Pm hi plane only (reuses bufA bytes)
    uint32_t* PmH = (uint32_t*)bufA_p;
    softmax_mix_kernel<<<dim3(32, 32), 256>>>(
        bufB_p, m_p, invl_p, Wpost, bpost, PmH);

    // 7) PV split-K x4, 1-term: o2part[part] = Pm @ v
    const __half* PmHb = (const __half*)PmH;
    gemm_lm<<<dim3(1, 16, NHEAD * 4), 256, GEMM_SMEM>>>(
        PmHb, PmHb, vth, o2pp, 2048, 2048, 2048, 1024,
        (long long)NN, (long long)HDIM * NTOK, 64, PSZ, 2, 1);

    // 8) combine partials -> o2 planes
    combine_pack4<<<2048, 256>>>(o2pp, o2pp + PSZ, o2pp + 2 * PSZ, o2pp + 3 * PSZ,
                                 o2h, o2l, 2048 * 1024);

    // 9) out = o2 @ Wout^T (split-K x4, 2-term, fp32 partials)
    gemm_lm<<<dim3(16, 16, 4), 256, GEMM_SMEM>>>(
        o2h, o2l, woh, outp, 1024, 1024, 1024, 1024,
        0, 0, 0, PSZ, 3, 2);

    // 10) combine out partials
    combine_out4<<<2048, 256>>>(outp, outp + PSZ, outp + 2 * PSZ, outp + 3 * PSZ,
                                out, 2048 * 1024);
}